// round 10
// baseline (speedup 1.0000x reference)
#include <cuda_runtime.h>
#include <math.h>
#include <stdint.h>
#include <stdio.h>

#define BB    32
#define LL    1024
#define BLROWS (BB*LL)          // 32768
#define HID   512
#define G4    2048
#define NUMC  1000
#define ATTD  80
#define LCTAS 128

// ---------------- scratch (static device globals: allocation-free) ----------
__device__ float g_sae  [(size_t)BLROWS * HID];    // LSTM input rows
__device__ float g_xpre [(size_t)BLROWS * G4];     // x @ W_ih^T + b
__device__ float g_hout [(size_t)BLROWS * HID];    // LSTM hidden states ("out")
__device__ float g_attT [(size_t)BLROWS * ATTD];   // tanh(out @ mlp_W^T + b)
__device__ float g_att  [BLROWS];                  // per-position attention logit
__device__ float g_final[(size_t)BLROWS * (2*HID)];// [attn_cum_1, out]
__device__ unsigned g_bar_count;
__device__ unsigned g_bar_phase;

// ---------------- embedding gather ------------------------------------------
__global__ void embed_kernel(const int* __restrict__ skill,
                             const int* __restrict__ answer,
                             const float* __restrict__ skill_table,
                             const float* __restrict__ answer_table)
{
    int idx = blockIdx.x * blockDim.x + threadIdx.x;   // over BLROWS*128 float4
    int row = idx >> 7;
    int q   = idx & 127;
    if (row >= BLROWS) return;
    int sk = skill[row];
    int an = answer[row];
    const float4* se = (const float4*)(skill_table  + (size_t)sk * 256);
    const float4* ae = (const float4*)(answer_table + (size_t)an * 256);
    float4 v;
    if (an == 1) v = (q < 64) ? se[q] : ae[q - 64];   // [skill, answer]
    else         v = (q < 64) ? ae[q] : se[q - 64];   // [answer, skill]
    ((float4*)g_sae)[(size_t)row * 128 + q] = v;
}

// ---------------- fp32 SGEMM: C = op(A @ B^T + bias1 + bias2) ---------------
// A: (M,K) row-major, B: (N,K) row-major, C: (M,N) row-major.
// M must be a multiple of 128. N,K arbitrary multiples of (1, 8). 256 threads.
// OP: 0 = identity, 1 = tanh, 2 = sigmoid
template<int OP>
__global__ void __launch_bounds__(256)
sgemm_nt(const float* __restrict__ A, const float* __restrict__ Bm,
         const float* __restrict__ bias1, const float* __restrict__ bias2,
         float* __restrict__ C, int M, int N, int K)
{
    __shared__ float As[8][128];
    __shared__ float Bs[8][128];

    const int tid = threadIdx.x;
    const int bm = blockIdx.y * 128;
    const int bn = blockIdx.x * 128;
    const int lr = tid >> 1;          // 0..127 tile row
    const int lc = (tid & 1) * 4;     // 0 or 4 (k offset)
    const int tx = tid & 15;
    const int ty = tid >> 4;

    float acc[8][8];
    #pragma unroll
    for (int i = 0; i < 8; i++)
        #pragma unroll
        for (int j = 0; j < 8; j++) acc[i][j] = 0.f;

    for (int k0 = 0; k0 < K; k0 += 8) {
        float4 a4 = *(const float4*)(A + (size_t)(bm + lr) * K + k0 + lc);
        As[lc+0][lr] = a4.x; As[lc+1][lr] = a4.y;
        As[lc+2][lr] = a4.z; As[lc+3][lr] = a4.w;

        float4 b4 = make_float4(0.f, 0.f, 0.f, 0.f);
        if (bn + lr < N)
            b4 = *(const float4*)(Bm + (size_t)(bn + lr) * K + k0 + lc);
        Bs[lc+0][lr] = b4.x; Bs[lc+1][lr] = b4.y;
        Bs[lc+2][lr] = b4.z; Bs[lc+3][lr] = b4.w;
        __syncthreads();

        #pragma unroll
        for (int kk = 0; kk < 8; kk++) {
            float a[8], b[8];
            *(float4*)(a)     = *(const float4*)&As[kk][ty*4];
            *(float4*)(a + 4) = *(const float4*)&As[kk][64 + ty*4];
            *(float4*)(b)     = *(const float4*)&Bs[kk][tx*4];
            *(float4*)(b + 4) = *(const float4*)&Bs[kk][64 + tx*4];
            #pragma unroll
            for (int i = 0; i < 8; i++)
                #pragma unroll
                for (int j = 0; j < 8; j++)
                    acc[i][j] += a[i] * b[j];
        }
        __syncthreads();
    }

    #pragma unroll
    for (int i = 0; i < 8; i++) {
        int row = bm + ((i < 4) ? (ty*4 + i) : (64 + ty*4 + i - 4));
        #pragma unroll
        for (int j = 0; j < 8; j++) {
            int col = bn + ((j < 4) ? (tx*4 + j) : (64 + tx*4 + j - 4));
            if (col < N) {
                float v = acc[i][j];
                if (bias1) v += bias1[col];
                if (bias2) v += bias2[col];
                if (OP == 1)      v = tanhf(v);
                else if (OP == 2) v = 1.f / (1.f + expf(-v));
                C[(size_t)row * N + col] = v;
            }
        }
    }
}

// ---------------- persistent LSTM (128 CTAs, grid barrier) ------------------
__device__ __forceinline__ void grid_barrier(int ncta)
{
    __threadfence();
    __syncthreads();
    if (threadIdx.x == 0) {
        volatile unsigned* ph_p = &g_bar_phase;
        unsigned ph = *ph_p;
        unsigned prev = atomicAdd(&g_bar_count, 1u);
        if (prev == (unsigned)(ncta - 1)) {
            g_bar_count = 0;
            __threadfence();
            *ph_p = ph + 1;
        } else {
            while (*ph_p == ph) { __nanosleep(32); }
        }
    }
    __syncthreads();
}

// Each CTA owns 4 hidden units (16 gate rows of W_hh) cached in SMEM forever.
// Per step: all CTAs read h[t-1] (global, L2), compute their 16 gate rows for
// all 32 batches, apply gates, write their 4 h values per batch, barrier.
__global__ void __launch_bounds__(256)
lstm_kernel(const float* __restrict__ xpre, const float* __restrict__ W_hh,
            float* __restrict__ hout)
{
    extern __shared__ float sm[];
    float* W_s = sm;                 // 16 rows x 516 (padded)
    float* h_s = sm + 16 * 516;      // 32 x 512
    __shared__ float gate_s[32][16];
    __shared__ float c_s[32][4];

    const int tid = threadIdx.x;
    const int cta = blockIdx.x;
    const int bg = tid >> 4;         // 0..15 -> batches (2*bg, 2*bg+1)
    const int r  = tid & 15;         // 0..15 -> gate row within slice
    const int b0 = bg * 2, b1 = bg * 2 + 1;
    const int grow = (r >> 2) * 512 + cta * 4 + (r & 3); // global gate row

    // load W_hh slice once
    for (int i = tid; i < 16 * 512; i += 256) {
        int rr = i >> 9, kk = i & 511;
        int gr = (rr >> 2) * 512 + cta * 4 + (rr & 3);
        W_s[rr * 516 + kk] = W_hh[(size_t)gr * 512 + kk];
    }
    if (tid < 128) c_s[tid >> 2][tid & 3] = 0.f;
    __syncthreads();

    const float4* Wr4 = (const float4*)(W_s + r * 516);
    const float4* H04 = (const float4*)(h_s + b0 * 512);
    const float4* H14 = (const float4*)(h_s + b1 * 512);

    for (int t = 0; t < LL; t++) {
        if (t > 0) {
            // broadcast h[t-1] for all 32 batches into SMEM (L2-only loads)
            for (int i = tid; i < 32 * 128; i += 256) {
                int b = i >> 7, kq = i & 127;
                ((float4*)h_s)[b * 128 + kq] =
                    __ldcg(((const float4*)hout) + ((size_t)b * LL + (t - 1)) * 128 + kq);
            }
        }
        __syncthreads();

        float4 A0 = make_float4(0,0,0,0), A1 = make_float4(0,0,0,0);
        if (t > 0) {
            #pragma unroll 8
            for (int kq = 0; kq < 128; kq++) {
                float4 w  = Wr4[kq];
                float4 x0 = H04[kq];
                float4 x1 = H14[kq];
                A0.x += w.x * x0.x; A0.y += w.y * x0.y;
                A0.z += w.z * x0.z; A0.w += w.w * x0.w;
                A1.x += w.x * x1.x; A1.y += w.y * x1.y;
                A1.z += w.z * x1.z; A1.w += w.w * x1.w;
            }
        }
        float acc0 = (A0.x + A0.y) + (A0.z + A0.w);
        float acc1 = (A1.x + A1.y) + (A1.z + A1.w);
        acc0 += __ldg(xpre + ((size_t)b0 * LL + t) * G4 + grow);
        acc1 += __ldg(xpre + ((size_t)b1 * LL + t) * G4 + grow);
        gate_s[b0][r] = acc0;
        gate_s[b1][r] = acc1;
        __syncthreads();

        if (tid < 128) {
            int b = tid >> 2, u = tid & 3;
            float gi = gate_s[b][u];
            float gf = gate_s[b][4 + u];
            float gc = gate_s[b][8 + u];
            float go = gate_s[b][12 + u];
            float i_ = 1.f / (1.f + expf(-gi));
            float f_ = 1.f / (1.f + expf(-gf));
            float gg = tanhf(gc);
            float o_ = 1.f / (1.f + expf(-go));
            float c  = f_ * c_s[b][u] + i_ * gg;
            c_s[b][u] = c;
            hout[((size_t)b * LL + t) * HID + cta * 4 + u] = o_ * tanhf(c);
        }
        grid_barrier(LCTAS);
    }
}

// ---------------- att[m] = attT[m,:] . sim_W --------------------------------
__global__ void att_reduce(const float* __restrict__ attT,
                           const float* __restrict__ simW,
                           float* __restrict__ att)
{
    int gid  = blockIdx.x * blockDim.x + threadIdx.x;
    int row  = gid >> 5;
    int lane = threadIdx.x & 31;
    if (row >= BLROWS) return;
    float v = 0.f;
    for (int a = lane; a < ATTD; a += 32)
        v += attT[(size_t)row * ATTD + a] * simW[a];
    #pragma unroll
    for (int o = 16; o; o >>= 1) v += __shfl_down_sync(0xffffffffu, v, o);
    if (lane == 0) att[row] = v;
}

// ---------------- causal attention via online-softmax prefix scan -----------
// alphas[b,i,j] = exp(att[b,j]) / sum_{k<=i} exp(att[b,k])  (j<=i)
// attn_out[b,i] = prefix_num / prefix_den; attn_cum_1 = exclusive cumsum.
// Writes final[b,i] = [attn_cum_1 (512), out (512)].
__global__ void attn_scan(const float* __restrict__ att,
                          const float* __restrict__ out,
                          float* __restrict__ finalbuf)
{
    int b = blockIdx.x;          // 32 blocks
    int h = threadIdx.x;         // 512 threads
    __shared__ float s_att[LL];
    for (int i = h; i < LL; i += 512) s_att[i] = att[(size_t)b * LL + i];
    __syncthreads();

    const float* ob = out      + (size_t)b * LL * HID;
    float*       fb = finalbuf + (size_t)b * LL * (2 * HID);

    float m = -1e30f, den = 0.f, num = 0.f, cum = 0.f;
    for (int i = 0; i < LL; i++) {
        float s     = s_att[i];
        float mnew  = fmaxf(m, s);
        float scale = expf(m - mnew);
        float alpha = expf(s - mnew);
        float ov    = ob[(size_t)i * HID + h];
        num = num * scale + alpha * ov;
        den = den * scale + alpha;
        m   = mnew;
        fb[(size_t)i * (2 * HID) + h]       = cum;   // attn_cum_1 (exclusive)
        fb[(size_t)i * (2 * HID) + HID + h] = ov;    // out
        cum += num / den;
    }
}

// ---------------- launch -----------------------------------------------------
extern "C" void kernel_launch(void* const* d_in, const int* in_sizes, int n_in,
                              void* d_out, int out_size)
{
    const int*   skill        = (const int*)  d_in[0];
    const int*   answer       = (const int*)  d_in[1];
    const float* skill_table  = (const float*)d_in[2];
    const float* answer_table = (const float*)d_in[3];
    const float* W_ih         = (const float*)d_in[4];
    const float* W_hh         = (const float*)d_in[5];
    const float* b_ih         = (const float*)d_in[6];
    const float* b_hh         = (const float*)d_in[7];
    const float* mlp_W        = (const float*)d_in[8];
    const float* mlp_b        = (const float*)d_in[9];
    const float* sim_W        = (const float*)d_in[10];
    const float* fc_W         = (const float*)d_in[11];
    const float* fc_b         = (const float*)d_in[12];
    float* outp = (float*)d_out;

    float *p_sae, *p_xpre, *p_hout, *p_attT, *p_att, *p_final;
    cudaGetSymbolAddress((void**)&p_sae,   g_sae);
    cudaGetSymbolAddress((void**)&p_xpre,  g_xpre);
    cudaGetSymbolAddress((void**)&p_hout,  g_hout);
    cudaGetSymbolAddress((void**)&p_attT,  g_attT);
    cudaGetSymbolAddress((void**)&p_att,   g_att);
    cudaGetSymbolAddress((void**)&p_final, g_final);

    // 1) embeddings -> sae
    {
        int total = BLROWS * 128;
        embed_kernel<<<total / 256, 256>>>(skill, answer, skill_table, answer_table);
    }

    // 2) x_pre = sae @ W_ih^T + (b_ih + b_hh)
    {
        dim3 grid(G4 / 128, BLROWS / 128);
        sgemm_nt<0><<<grid, 256>>>(p_sae, W_ih, b_ih, b_hh, p_xpre,
                                   BLROWS, G4, HID);
    }

    // 3) LSTM recurrence (persistent, grid barrier)
    {
        const int smem = (16 * 516 + 32 * 512) * (int)sizeof(float);  // 98560
        cudaFuncSetAttribute(lstm_kernel,
                             cudaFuncAttributeMaxDynamicSharedMemorySize, smem);
        lstm_kernel<<<LCTAS, 256, smem>>>(p_xpre, W_hh, p_hout);
    }

    // 4) attT = tanh(out @ mlp_W^T + mlp_b)
    {
        dim3 grid((ATTD + 127) / 128, BLROWS / 128);
        sgemm_nt<1><<<grid, 256>>>(p_hout, mlp_W, mlp_b, nullptr, p_attT,
                                   BLROWS, ATTD, HID);
    }

    // 5) att = attT . sim_W
    att_reduce<<<(BLROWS * 32) / 256, 256>>>(p_attT, sim_W, p_att);

    // 6) online-softmax prefix scan -> final = [attn_cum_1, out]
    attn_scan<<<BB, 512>>>(p_att, p_hout, p_final);

    // 7) res = sigmoid(final @ fc_W^T + fc_b)
    {
        dim3 grid((NUMC + 127) / 128, BLROWS / 128);
        sgemm_nt<2><<<grid, 256>>>(p_final, fc_W, fc_b, nullptr, outp,
                                   BLROWS, NUMC, 2 * HID);
    }
}

// round 11
// speedup vs baseline: 1.0042x; 1.0042x over previous
#include <cuda_runtime.h>
#include <math.h>
#include <stdint.h>
#include <stdio.h>

#define BB    32
#define LL    1024
#define BLROWS (BB*LL)          // 32768
#define HID   512
#define G4    2048
#define NUMC  1000
#define ATTD  80
#define LCTAS 128

// ---------------- scratch (static device globals: allocation-free) ----------
__device__ float g_sae  [(size_t)BLROWS * HID];    // LSTM input rows
__device__ float g_xpre [(size_t)BLROWS * G4];     // x @ W_ih^T + b
__device__ float g_hout [(size_t)BLROWS * HID];    // LSTM hidden states ("out")
__device__ float g_attT [(size_t)BLROWS * ATTD];   // tanh(out @ mlp_W^T + b)
__device__ float g_att  [BLROWS];                  // per-position attention logit
__device__ float g_final[(size_t)BLROWS * (2*HID)];// [attn_cum_1, out]
__device__ unsigned g_bar_count;
__device__ unsigned g_bar_phase;

// ---------------- embedding gather ------------------------------------------
__global__ void embed_kernel(const int* __restrict__ skill,
                             const int* __restrict__ answer,
                             const float* __restrict__ skill_table,
                             const float* __restrict__ answer_table)
{
    int idx = blockIdx.x * blockDim.x + threadIdx.x;   // over BLROWS*128 float4
    int row = idx >> 7;
    int q   = idx & 127;
    if (row >= BLROWS) return;
    int sk = skill[row];
    int an = answer[row];
    const float4* se = (const float4*)(skill_table  + (size_t)sk * 256);
    const float4* ae = (const float4*)(answer_table + (size_t)an * 256);
    float4 v;
    if (an == 1) v = (q < 64) ? se[q] : ae[q - 64];   // [skill, answer]
    else         v = (q < 64) ? ae[q] : se[q - 64];   // [answer, skill]
    ((float4*)g_sae)[(size_t)row * 128 + q] = v;
}

// ---------------- fp32 SGEMM: C = op(A @ B^T + bias1 + bias2) ---------------
// A: (M,K) row-major, B: (N,K) row-major, C: (M,N) row-major.
// M must be a multiple of 128. N,K arbitrary multiples of (1, 8). 256 threads.
// OP: 0 = identity, 1 = tanh, 2 = sigmoid
template<int OP>
__global__ void __launch_bounds__(256)
sgemm_nt(const float* __restrict__ A, const float* __restrict__ Bm,
         const float* __restrict__ bias1, const float* __restrict__ bias2,
         float* __restrict__ C, int M, int N, int K)
{
    __shared__ float As[8][128];
    __shared__ float Bs[8][128];

    const int tid = threadIdx.x;
    const int bm = blockIdx.y * 128;
    const int bn = blockIdx.x * 128;
    const int lr = tid >> 1;          // 0..127 tile row
    const int lc = (tid & 1) * 4;     // 0 or 4 (k offset)
    const int tx = tid & 15;
    const int ty = tid >> 4;

    float acc[8][8];
    #pragma unroll
    for (int i = 0; i < 8; i++)
        #pragma unroll
        for (int j = 0; j < 8; j++) acc[i][j] = 0.f;

    for (int k0 = 0; k0 < K; k0 += 8) {
        float4 a4 = *(const float4*)(A + (size_t)(bm + lr) * K + k0 + lc);
        As[lc+0][lr] = a4.x; As[lc+1][lr] = a4.y;
        As[lc+2][lr] = a4.z; As[lc+3][lr] = a4.w;

        float4 b4 = make_float4(0.f, 0.f, 0.f, 0.f);
        if (bn + lr < N)
            b4 = *(const float4*)(Bm + (size_t)(bn + lr) * K + k0 + lc);
        Bs[lc+0][lr] = b4.x; Bs[lc+1][lr] = b4.y;
        Bs[lc+2][lr] = b4.z; Bs[lc+3][lr] = b4.w;
        __syncthreads();

        #pragma unroll
        for (int kk = 0; kk < 8; kk++) {
            float a[8], b[8];
            *(float4*)(a)     = *(const float4*)&As[kk][ty*4];
            *(float4*)(a + 4) = *(const float4*)&As[kk][64 + ty*4];
            *(float4*)(b)     = *(const float4*)&Bs[kk][tx*4];
            *(float4*)(b + 4) = *(const float4*)&Bs[kk][64 + tx*4];
            #pragma unroll
            for (int i = 0; i < 8; i++)
                #pragma unroll
                for (int j = 0; j < 8; j++)
                    acc[i][j] += a[i] * b[j];
        }
        __syncthreads();
    }

    #pragma unroll
    for (int i = 0; i < 8; i++) {
        int row = bm + ((i < 4) ? (ty*4 + i) : (64 + ty*4 + i - 4));
        #pragma unroll
        for (int j = 0; j < 8; j++) {
            int col = bn + ((j < 4) ? (tx*4 + j) : (64 + tx*4 + j - 4));
            if (col < N) {
                float v = acc[i][j];
                if (bias1) v += bias1[col];
                if (bias2) v += bias2[col];
                if (OP == 1)      v = tanhf(v);
                else if (OP == 2) v = 1.f / (1.f + expf(-v));
                C[(size_t)row * N + col] = v;
            }
        }
    }
}

// ---------------- persistent LSTM (128 CTAs, grid barrier) ------------------
__device__ __forceinline__ void grid_barrier(int ncta)
{
    __threadfence();
    __syncthreads();
    if (threadIdx.x == 0) {
        volatile unsigned* ph_p = &g_bar_phase;
        unsigned ph = *ph_p;
        unsigned prev = atomicAdd(&g_bar_count, 1u);
        if (prev == (unsigned)(ncta - 1)) {
            g_bar_count = 0;
            __threadfence();
            *ph_p = ph + 1;
        } else {
            while (*ph_p == ph) { __nanosleep(32); }
        }
    }
    __syncthreads();
}

// Each CTA owns 4 hidden units (16 gate rows of W_hh) cached in SMEM forever.
// Per step: all CTAs read h[t-1] (global, L2), compute their 16 gate rows for
// all 32 batches, apply gates, write their 4 h values per batch, barrier.
__global__ void __launch_bounds__(256)
lstm_kernel(const float* __restrict__ xpre, const float* __restrict__ W_hh,
            float* __restrict__ hout)
{
    extern __shared__ float sm[];
    float* W_s = sm;                 // 16 rows x 516 (padded)
    float* h_s = sm + 16 * 516;      // 32 x 512
    __shared__ float gate_s[32][16];
    __shared__ float c_s[32][4];

    const int tid = threadIdx.x;
    const int cta = blockIdx.x;
    const int bg = tid >> 4;         // 0..15 -> batches (2*bg, 2*bg+1)
    const int r  = tid & 15;         // 0..15 -> gate row within slice
    const int b0 = bg * 2, b1 = bg * 2 + 1;
    const int grow = (r >> 2) * 512 + cta * 4 + (r & 3); // global gate row

    // load W_hh slice once
    for (int i = tid; i < 16 * 512; i += 256) {
        int rr = i >> 9, kk = i & 511;
        int gr = (rr >> 2) * 512 + cta * 4 + (rr & 3);
        W_s[rr * 516 + kk] = W_hh[(size_t)gr * 512 + kk];
    }
    if (tid < 128) c_s[tid >> 2][tid & 3] = 0.f;
    __syncthreads();

    const float4* Wr4 = (const float4*)(W_s + r * 516);
    const float4* H04 = (const float4*)(h_s + b0 * 512);
    const float4* H14 = (const float4*)(h_s + b1 * 512);

    for (int t = 0; t < LL; t++) {
        if (t > 0) {
            // broadcast h[t-1] for all 32 batches into SMEM (L2-only loads)
            for (int i = tid; i < 32 * 128; i += 256) {
                int b = i >> 7, kq = i & 127;
                ((float4*)h_s)[b * 128 + kq] =
                    __ldcg(((const float4*)hout) + ((size_t)b * LL + (t - 1)) * 128 + kq);
            }
        }
        __syncthreads();

        float4 A0 = make_float4(0,0,0,0), A1 = make_float4(0,0,0,0);
        if (t > 0) {
            #pragma unroll 8
            for (int kq = 0; kq < 128; kq++) {
                float4 w  = Wr4[kq];
                float4 x0 = H04[kq];
                float4 x1 = H14[kq];
                A0.x += w.x * x0.x; A0.y += w.y * x0.y;
                A0.z += w.z * x0.z; A0.w += w.w * x0.w;
                A1.x += w.x * x1.x; A1.y += w.y * x1.y;
                A1.z += w.z * x1.z; A1.w += w.w * x1.w;
            }
        }
        float acc0 = (A0.x + A0.y) + (A0.z + A0.w);
        float acc1 = (A1.x + A1.y) + (A1.z + A1.w);
        acc0 += __ldg(xpre + ((size_t)b0 * LL + t) * G4 + grow);
        acc1 += __ldg(xpre + ((size_t)b1 * LL + t) * G4 + grow);
        gate_s[b0][r] = acc0;
        gate_s[b1][r] = acc1;
        __syncthreads();

        if (tid < 128) {
            int b = tid >> 2, u = tid & 3;
            float gi = gate_s[b][u];
            float gf = gate_s[b][4 + u];
            float gc = gate_s[b][8 + u];
            float go = gate_s[b][12 + u];
            float i_ = 1.f / (1.f + expf(-gi));
            float f_ = 1.f / (1.f + expf(-gf));
            float gg = tanhf(gc);
            float o_ = 1.f / (1.f + expf(-go));
            float c  = f_ * c_s[b][u] + i_ * gg;
            c_s[b][u] = c;
            hout[((size_t)b * LL + t) * HID + cta * 4 + u] = o_ * tanhf(c);
        }
        grid_barrier(LCTAS);
    }
}

// ---------------- att[m] = attT[m,:] . sim_W --------------------------------
__global__ void att_reduce(const float* __restrict__ attT,
                           const float* __restrict__ simW,
                           float* __restrict__ att)
{
    int gid  = blockIdx.x * blockDim.x + threadIdx.x;
    int row  = gid >> 5;
    int lane = threadIdx.x & 31;
    if (row >= BLROWS) return;
    float v = 0.f;
    for (int a = lane; a < ATTD; a += 32)
        v += attT[(size_t)row * ATTD + a] * simW[a];
    #pragma unroll
    for (int o = 16; o; o >>= 1) v += __shfl_down_sync(0xffffffffu, v, o);
    if (lane == 0) att[row] = v;
}

// ---------------- causal attention via online-softmax prefix scan -----------
// alphas[b,i,j] = exp(att[b,j]) / sum_{k<=i} exp(att[b,k])  (j<=i)
// attn_out[b,i] = prefix_num / prefix_den; attn_cum_1 = exclusive cumsum.
// Writes final[b,i] = [attn_cum_1 (512), out (512)].
__global__ void attn_scan(const float* __restrict__ att,
                          const float* __restrict__ out,
                          float* __restrict__ finalbuf)
{
    int b = blockIdx.x;          // 32 blocks
    int h = threadIdx.x;         // 512 threads
    __shared__ float s_att[LL];
    for (int i = h; i < LL; i += 512) s_att[i] = att[(size_t)b * LL + i];
    __syncthreads();

    const float* ob = out      + (size_t)b * LL * HID;
    float*       fb = finalbuf + (size_t)b * LL * (2 * HID);

    float m = -1e30f, den = 0.f, num = 0.f, cum = 0.f;
    for (int i = 0; i < LL; i++) {
        float s     = s_att[i];
        float mnew  = fmaxf(m, s);
        float scale = expf(m - mnew);
        float alpha = expf(s - mnew);
        float ov    = ob[(size_t)i * HID + h];
        num = num * scale + alpha * ov;
        den = den * scale + alpha;
        m   = mnew;
        fb[(size_t)i * (2 * HID) + h]       = cum;   // attn_cum_1 (exclusive)
        fb[(size_t)i * (2 * HID) + HID + h] = ov;    // out
        cum += num / den;
    }
}

// ---------------- launch -----------------------------------------------------
extern "C" void kernel_launch(void* const* d_in, const int* in_sizes, int n_in,
                              void* d_out, int out_size)
{
    const int*   skill        = (const int*)  d_in[0];
    const int*   answer       = (const int*)  d_in[1];
    const float* skill_table  = (const float*)d_in[2];
    const float* answer_table = (const float*)d_in[3];
    const float* W_ih         = (const float*)d_in[4];
    const float* W_hh         = (const float*)d_in[5];
    const float* b_ih         = (const float*)d_in[6];
    const float* b_hh         = (const float*)d_in[7];
    const float* mlp_W        = (const float*)d_in[8];
    const float* mlp_b        = (const float*)d_in[9];
    const float* sim_W        = (const float*)d_in[10];
    const float* fc_W         = (const float*)d_in[11];
    const float* fc_b         = (const float*)d_in[12];
    float* outp = (float*)d_out;

    float *p_sae, *p_xpre, *p_hout, *p_attT, *p_att, *p_final;
    cudaGetSymbolAddress((void**)&p_sae,   g_sae);
    cudaGetSymbolAddress((void**)&p_xpre,  g_xpre);
    cudaGetSymbolAddress((void**)&p_hout,  g_hout);
    cudaGetSymbolAddress((void**)&p_attT,  g_attT);
    cudaGetSymbolAddress((void**)&p_att,   g_att);
    cudaGetSymbolAddress((void**)&p_final, g_final);

    // 1) embeddings -> sae
    {
        int total = BLROWS * 128;
        embed_kernel<<<total / 256, 256>>>(skill, answer, skill_table, answer_table);
    }

    // 2) x_pre = sae @ W_ih^T + (b_ih + b_hh)
    {
        dim3 grid(G4 / 128, BLROWS / 128);
        sgemm_nt<0><<<grid, 256>>>(p_sae, W_ih, b_ih, b_hh, p_xpre,
                                   BLROWS, G4, HID);
    }

    // 3) LSTM recurrence (persistent, grid barrier)
    {
        const int smem = (16 * 516 + 32 * 512) * (int)sizeof(float);  // 98560
        cudaFuncSetAttribute(lstm_kernel,
                             cudaFuncAttributeMaxDynamicSharedMemorySize, smem);
        lstm_kernel<<<LCTAS, 256, smem>>>(p_xpre, W_hh, p_hout);
    }

    // 4) attT = tanh(out @ mlp_W^T + mlp_b)
    {
        dim3 grid((ATTD + 127) / 128, BLROWS / 128);
        sgemm_nt<1><<<grid, 256>>>(p_hout, mlp_W, mlp_b, nullptr, p_attT,
                                   BLROWS, ATTD, HID);
    }

    // 5) att = attT . sim_W
    att_reduce<<<(BLROWS * 32) / 256, 256>>>(p_attT, sim_W, p_att);

    // 6) online-softmax prefix scan -> final = [attn_cum_1, out]
    attn_scan<<<BB, 512>>>(p_att, p_hout, p_final);

    // 7) res = sigmoid(final @ fc_W^T + fc_b)
    {
        dim3 grid((NUMC + 127) / 128, BLROWS / 128);
        sgemm_nt<2><<<grid, 256>>>(p_final, fc_W, fc_b, nullptr, outp,
                                   BLROWS, NUMC, 2 * HID);
    }
}

// round 12
// speedup vs baseline: 1.0061x; 1.0019x over previous
#include <cuda_runtime.h>
#include <math.h>
#include <stdint.h>
#include <stdio.h>

#define BB    32
#define LL    1024
#define BLROWS (BB*LL)          // 32768
#define HID   512
#define G4    2048
#define NUMC  1000
#define ATTD  80
#define LCTAS 128

// ---------------- scratch (static device globals: allocation-free) ----------
__device__ float g_sae  [(size_t)BLROWS * HID];    // LSTM input rows
__device__ float g_xpre [(size_t)BLROWS * G4];     // x @ W_ih^T + b
__device__ float g_hout [(size_t)BLROWS * HID];    // LSTM hidden states ("out")
__device__ float g_attT [(size_t)BLROWS * ATTD];   // tanh(out @ mlp_W^T + b)
__device__ float g_att  [BLROWS];                  // per-position attention logit
__device__ float g_final[(size_t)BLROWS * (2*HID)];// [attn_cum_1, out]
__device__ unsigned g_bar_count;
__device__ unsigned g_bar_phase;

// ---------------- embedding gather ------------------------------------------
__global__ void embed_kernel(const int* __restrict__ skill,
                             const int* __restrict__ answer,
                             const float* __restrict__ skill_table,
                             const float* __restrict__ answer_table)
{
    int idx = blockIdx.x * blockDim.x + threadIdx.x;   // over BLROWS*128 float4
    int row = idx >> 7;
    int q   = idx & 127;
    if (row >= BLROWS) return;
    int sk = skill[row];
    int an = answer[row];
    const float4* se = (const float4*)(skill_table  + (size_t)sk * 256);
    const float4* ae = (const float4*)(answer_table + (size_t)an * 256);
    float4 v;
    if (an == 1) v = (q < 64) ? se[q] : ae[q - 64];   // [skill, answer]
    else         v = (q < 64) ? ae[q] : se[q - 64];   // [answer, skill]
    ((float4*)g_sae)[(size_t)row * 128 + q] = v;
}

// ---------------- fp32 SGEMM: C = op(A @ B^T + bias1 + bias2) ---------------
// A: (M,K) row-major, B: (N,K) row-major, C: (M,N) row-major.
// M must be a multiple of 128. N,K arbitrary multiples of (1, 8). 256 threads.
// OP: 0 = identity, 1 = tanh, 2 = sigmoid
template<int OP>
__global__ void __launch_bounds__(256)
sgemm_nt(const float* __restrict__ A, const float* __restrict__ Bm,
         const float* __restrict__ bias1, const float* __restrict__ bias2,
         float* __restrict__ C, int M, int N, int K)
{
    __shared__ float As[8][128];
    __shared__ float Bs[8][128];

    const int tid = threadIdx.x;
    const int bm = blockIdx.y * 128;
    const int bn = blockIdx.x * 128;
    const int lr = tid >> 1;          // 0..127 tile row
    const int lc = (tid & 1) * 4;     // 0 or 4 (k offset)
    const int tx = tid & 15;
    const int ty = tid >> 4;

    float acc[8][8];
    #pragma unroll
    for (int i = 0; i < 8; i++)
        #pragma unroll
        for (int j = 0; j < 8; j++) acc[i][j] = 0.f;

    for (int k0 = 0; k0 < K; k0 += 8) {
        float4 a4 = *(const float4*)(A + (size_t)(bm + lr) * K + k0 + lc);
        As[lc+0][lr] = a4.x; As[lc+1][lr] = a4.y;
        As[lc+2][lr] = a4.z; As[lc+3][lr] = a4.w;

        float4 b4 = make_float4(0.f, 0.f, 0.f, 0.f);
        if (bn + lr < N)
            b4 = *(const float4*)(Bm + (size_t)(bn + lr) * K + k0 + lc);
        Bs[lc+0][lr] = b4.x; Bs[lc+1][lr] = b4.y;
        Bs[lc+2][lr] = b4.z; Bs[lc+3][lr] = b4.w;
        __syncthreads();

        #pragma unroll
        for (int kk = 0; kk < 8; kk++) {
            float a[8], b[8];
            *(float4*)(a)     = *(const float4*)&As[kk][ty*4];
            *(float4*)(a + 4) = *(const float4*)&As[kk][64 + ty*4];
            *(float4*)(b)     = *(const float4*)&Bs[kk][tx*4];
            *(float4*)(b + 4) = *(const float4*)&Bs[kk][64 + tx*4];
            #pragma unroll
            for (int i = 0; i < 8; i++)
                #pragma unroll
                for (int j = 0; j < 8; j++)
                    acc[i][j] += a[i] * b[j];
        }
        __syncthreads();
    }

    #pragma unroll
    for (int i = 0; i < 8; i++) {
        int row = bm + ((i < 4) ? (ty*4 + i) : (64 + ty*4 + i - 4));
        #pragma unroll
        for (int j = 0; j < 8; j++) {
            int col = bn + ((j < 4) ? (tx*4 + j) : (64 + tx*4 + j - 4));
            if (col < N) {
                float v = acc[i][j];
                if (bias1) v += bias1[col];
                if (bias2) v += bias2[col];
                if (OP == 1)      v = tanhf(v);
                else if (OP == 2) v = 1.f / (1.f + expf(-v));
                C[(size_t)row * N + col] = v;
            }
        }
    }
}

// ---------------- persistent LSTM (128 CTAs, grid barrier) ------------------
__device__ __forceinline__ void grid_barrier(int ncta)
{
    __threadfence();
    __syncthreads();
    if (threadIdx.x == 0) {
        volatile unsigned* ph_p = &g_bar_phase;
        unsigned ph = *ph_p;
        unsigned prev = atomicAdd(&g_bar_count, 1u);
        if (prev == (unsigned)(ncta - 1)) {
            g_bar_count = 0;
            __threadfence();
            *ph_p = ph + 1;
        } else {
            while (*ph_p == ph) { __nanosleep(32); }
        }
    }
    __syncthreads();
}

// Each CTA owns 4 hidden units (16 gate rows of W_hh) cached in SMEM forever.
// Per step: all CTAs read h[t-1] (global, L2), compute their 16 gate rows for
// all 32 batches, apply gates, write their 4 h values per batch, barrier.
__global__ void __launch_bounds__(256)
lstm_kernel(const float* __restrict__ xpre, const float* __restrict__ W_hh,
            float* __restrict__ hout)
{
    extern __shared__ float sm[];
    float* W_s = sm;                 // 16 rows x 516 (padded)
    float* h_s = sm + 16 * 516;      // 32 x 512
    __shared__ float gate_s[32][16];
    __shared__ float c_s[32][4];

    const int tid = threadIdx.x;
    const int cta = blockIdx.x;
    const int bg = tid >> 4;         // 0..15 -> batches (2*bg, 2*bg+1)
    const int r  = tid & 15;         // 0..15 -> gate row within slice
    const int b0 = bg * 2, b1 = bg * 2 + 1;
    const int grow = (r >> 2) * 512 + cta * 4 + (r & 3); // global gate row

    // load W_hh slice once
    for (int i = tid; i < 16 * 512; i += 256) {
        int rr = i >> 9, kk = i & 511;
        int gr = (rr >> 2) * 512 + cta * 4 + (rr & 3);
        W_s[rr * 516 + kk] = W_hh[(size_t)gr * 512 + kk];
    }
    if (tid < 128) c_s[tid >> 2][tid & 3] = 0.f;
    __syncthreads();

    const float4* Wr4 = (const float4*)(W_s + r * 516);
    const float4* H04 = (const float4*)(h_s + b0 * 512);
    const float4* H14 = (const float4*)(h_s + b1 * 512);

    for (int t = 0; t < LL; t++) {
        if (t > 0) {
            // broadcast h[t-1] for all 32 batches into SMEM (L2-only loads)
            for (int i = tid; i < 32 * 128; i += 256) {
                int b = i >> 7, kq = i & 127;
                ((float4*)h_s)[b * 128 + kq] =
                    __ldcg(((const float4*)hout) + ((size_t)b * LL + (t - 1)) * 128 + kq);
            }
        }
        __syncthreads();

        float4 A0 = make_float4(0,0,0,0), A1 = make_float4(0,0,0,0);
        if (t > 0) {
            #pragma unroll 8
            for (int kq = 0; kq < 128; kq++) {
                float4 w  = Wr4[kq];
                float4 x0 = H04[kq];
                float4 x1 = H14[kq];
                A0.x += w.x * x0.x; A0.y += w.y * x0.y;
                A0.z += w.z * x0.z; A0.w += w.w * x0.w;
                A1.x += w.x * x1.x; A1.y += w.y * x1.y;
                A1.z += w.z * x1.z; A1.w += w.w * x1.w;
            }
        }
        float acc0 = (A0.x + A0.y) + (A0.z + A0.w);
        float acc1 = (A1.x + A1.y) + (A1.z + A1.w);
        acc0 += __ldg(xpre + ((size_t)b0 * LL + t) * G4 + grow);
        acc1 += __ldg(xpre + ((size_t)b1 * LL + t) * G4 + grow);
        gate_s[b0][r] = acc0;
        gate_s[b1][r] = acc1;
        __syncthreads();

        if (tid < 128) {
            int b = tid >> 2, u = tid & 3;
            float gi = gate_s[b][u];
            float gf = gate_s[b][4 + u];
            float gc = gate_s[b][8 + u];
            float go = gate_s[b][12 + u];
            float i_ = 1.f / (1.f + expf(-gi));
            float f_ = 1.f / (1.f + expf(-gf));
            float gg = tanhf(gc);
            float o_ = 1.f / (1.f + expf(-go));
            float c  = f_ * c_s[b][u] + i_ * gg;
            c_s[b][u] = c;
            hout[((size_t)b * LL + t) * HID + cta * 4 + u] = o_ * tanhf(c);
        }
        grid_barrier(LCTAS);
    }
}

// ---------------- att[m] = attT[m,:] . sim_W --------------------------------
__global__ void att_reduce(const float* __restrict__ attT,
                           const float* __restrict__ simW,
                           float* __restrict__ att)
{
    int gid  = blockIdx.x * blockDim.x + threadIdx.x;
    int row  = gid >> 5;
    int lane = threadIdx.x & 31;
    if (row >= BLROWS) return;
    float v = 0.f;
    for (int a = lane; a < ATTD; a += 32)
        v += attT[(size_t)row * ATTD + a] * simW[a];
    #pragma unroll
    for (int o = 16; o; o >>= 1) v += __shfl_down_sync(0xffffffffu, v, o);
    if (lane == 0) att[row] = v;
}

// ---------------- causal attention via online-softmax prefix scan -----------
// alphas[b,i,j] = exp(att[b,j]) / sum_{k<=i} exp(att[b,k])  (j<=i)
// attn_out[b,i] = prefix_num / prefix_den; attn_cum_1 = exclusive cumsum.
// Writes final[b,i] = [attn_cum_1 (512), out (512)].
__global__ void attn_scan(const float* __restrict__ att,
                          const float* __restrict__ out,
                          float* __restrict__ finalbuf)
{
    int b = blockIdx.x;          // 32 blocks
    int h = threadIdx.x;         // 512 threads
    __shared__ float s_att[LL];
    for (int i = h; i < LL; i += 512) s_att[i] = att[(size_t)b * LL + i];
    __syncthreads();

    const float* ob = out      + (size_t)b * LL * HID;
    float*       fb = finalbuf + (size_t)b * LL * (2 * HID);

    float m = -1e30f, den = 0.f, num = 0.f, cum = 0.f;
    for (int i = 0; i < LL; i++) {
        float s     = s_att[i];
        float mnew  = fmaxf(m, s);
        float scale = expf(m - mnew);
        float alpha = expf(s - mnew);
        float ov    = ob[(size_t)i * HID + h];
        num = num * scale + alpha * ov;
        den = den * scale + alpha;
        m   = mnew;
        fb[(size_t)i * (2 * HID) + h]       = cum;   // attn_cum_1 (exclusive)
        fb[(size_t)i * (2 * HID) + HID + h] = ov;    // out
        cum += num / den;
    }
}

// ---------------- launch -----------------------------------------------------
extern "C" void kernel_launch(void* const* d_in, const int* in_sizes, int n_in,
                              void* d_out, int out_size)
{
    const int*   skill        = (const int*)  d_in[0];
    const int*   answer       = (const int*)  d_in[1];
    const float* skill_table  = (const float*)d_in[2];
    const float* answer_table = (const float*)d_in[3];
    const float* W_ih         = (const float*)d_in[4];
    const float* W_hh         = (const float*)d_in[5];
    const float* b_ih         = (const float*)d_in[6];
    const float* b_hh         = (const float*)d_in[7];
    const float* mlp_W        = (const float*)d_in[8];
    const float* mlp_b        = (const float*)d_in[9];
    const float* sim_W        = (const float*)d_in[10];
    const float* fc_W         = (const float*)d_in[11];
    const float* fc_b         = (const float*)d_in[12];
    float* outp = (float*)d_out;

    float *p_sae, *p_xpre, *p_hout, *p_attT, *p_att, *p_final;
    cudaGetSymbolAddress((void**)&p_sae,   g_sae);
    cudaGetSymbolAddress((void**)&p_xpre,  g_xpre);
    cudaGetSymbolAddress((void**)&p_hout,  g_hout);
    cudaGetSymbolAddress((void**)&p_attT,  g_attT);
    cudaGetSymbolAddress((void**)&p_att,   g_att);
    cudaGetSymbolAddress((void**)&p_final, g_final);

    // 1) embeddings -> sae
    {
        int total = BLROWS * 128;
        embed_kernel<<<total / 256, 256>>>(skill, answer, skill_table, answer_table);
    }

    // 2) x_pre = sae @ W_ih^T + (b_ih + b_hh)
    {
        dim3 grid(G4 / 128, BLROWS / 128);
        sgemm_nt<0><<<grid, 256>>>(p_sae, W_ih, b_ih, b_hh, p_xpre,
                                   BLROWS, G4, HID);
    }

    // 3) LSTM recurrence (persistent, grid barrier)
    {
        const int smem = (16 * 516 + 32 * 512) * (int)sizeof(float);  // 98560
        cudaFuncSetAttribute(lstm_kernel,
                             cudaFuncAttributeMaxDynamicSharedMemorySize, smem);
        lstm_kernel<<<LCTAS, 256, smem>>>(p_xpre, W_hh, p_hout);
    }

    // 4) attT = tanh(out @ mlp_W^T + mlp_b)
    {
        dim3 grid((ATTD + 127) / 128, BLROWS / 128);
        sgemm_nt<1><<<grid, 256>>>(p_hout, mlp_W, mlp_b, nullptr, p_attT,
                                   BLROWS, ATTD, HID);
    }

    // 5) att = attT . sim_W
    att_reduce<<<(BLROWS * 32) / 256, 256>>>(p_attT, sim_W, p_att);

    // 6) online-softmax prefix scan -> final = [attn_cum_1, out]
    attn_scan<<<BB, 512>>>(p_att, p_hout, p_final);

    // 7) res = sigmoid(final @ fc_W^T + fc_b)
    {
        dim3 grid((NUMC + 127) / 128, BLROWS / 128);
        sgemm_nt<2><<<grid, 256>>>(p_final, fc_W, fc_b, nullptr, outp,
                                   BLROWS, NUMC, 2 * HID);
    }
}

// round 13
// speedup vs baseline: 1.1682x; 1.1611x over previous
#include <cuda_runtime.h>
#include <math.h>
#include <stdint.h>
#include <stdio.h>

#define BB    32
#define LL    1024
#define BLROWS (BB*LL)          // 32768
#define HID   512
#define G4    2048
#define NUMC  1000
#define ATTD  80
#define LCTAS 128

// ---------------- scratch (static device globals: allocation-free) ----------
__device__ float g_sae  [(size_t)BLROWS * HID];    // LSTM input rows
__device__ float g_xpre [(size_t)BLROWS * G4];     // x @ W_ih^T + b
__device__ float g_hout [(size_t)BLROWS * HID];    // LSTM hidden states ("out")
__device__ float g_attT [(size_t)BLROWS * ATTD];   // tanh(out @ mlp_W^T + b)
__device__ float g_att  [BLROWS];                  // per-position attention logit
__device__ float g_final[(size_t)BLROWS * (2*HID)];// [attn_cum_1, out]
__device__ unsigned g_bar_count;
__device__ unsigned g_bar_phase;

// ---------------- embedding gather ------------------------------------------
__global__ void embed_kernel(const int* __restrict__ skill,
                             const int* __restrict__ answer,
                             const float* __restrict__ skill_table,
                             const float* __restrict__ answer_table)
{
    int idx = blockIdx.x * blockDim.x + threadIdx.x;   // over BLROWS*128 float4
    int row = idx >> 7;
    int q   = idx & 127;
    if (row >= BLROWS) return;
    int sk = skill[row];
    int an = answer[row];
    const float4* se = (const float4*)(skill_table  + (size_t)sk * 256);
    const float4* ae = (const float4*)(answer_table + (size_t)an * 256);
    float4 v;
    if (an == 1) v = (q < 64) ? se[q] : ae[q - 64];   // [skill, answer]
    else         v = (q < 64) ? ae[q] : se[q - 64];   // [answer, skill]
    ((float4*)g_sae)[(size_t)row * 128 + q] = v;
}

// ---------------- tf32 tensor-core GEMM: C = op(A @ B^T + bias1 + bias2) ----
// A: (M,K) row-major fp32, B: (N,K) row-major fp32, C: (M,N) row-major fp32.
// M multiple of 128, K multiple of 32, N arbitrary even. 256 threads.
// CTA tile 128x128x32; 8 warps (2M x 4N); warp tile 64x32; mma m16n8k8.
// SMEM is staged in mma-fragment-major layout so frag loads are single
// conflict-free LDS.128 / LDS.64.
// OP: 0 = identity, 1 = tanh, 2 = sigmoid

__device__ __forceinline__ uint32_t f2tf32(float v) {
    uint32_t u;
    asm("cvt.rna.tf32.f32 %0, %1;" : "=r"(u) : "f"(v));
    return u;
}

template<int OP>
__global__ void __launch_bounds__(256)
tf32gemm_nt(const float* __restrict__ A, const float* __restrict__ Bm,
            const float* __restrict__ bias1, const float* __restrict__ bias2,
            float* __restrict__ C, int M, int N, int K)
{
    // A frags: [ks(4)][mtile(8)][lane(32)][reg(4)]  = 4096 u32 (16 KB)
    // B frags: [ks(4)][ntile(16)][lane(32)][reg(2)] = 4096 u32 (16 KB)
    __shared__ uint32_t As[4096];
    __shared__ uint32_t Bs[4096];

    const int tid  = threadIdx.x;
    const int warp = tid >> 5;
    const int lane = tid & 31;
    const int wm   = warp >> 2;      // 0..1
    const int wn   = warp & 3;       // 0..3
    const int bm   = blockIdx.y * 128;
    const int bn   = blockIdx.x * 128;

    float acc[4][4][4];
    #pragma unroll
    for (int i = 0; i < 4; i++)
        #pragma unroll
        for (int j = 0; j < 4; j++)
            #pragma unroll
            for (int r = 0; r < 4; r++) acc[i][j][r] = 0.f;

    for (int kt = 0; kt < K; kt += 32) {
        // ---- stage A and B tiles into fragment-major SMEM ----
        #pragma unroll
        for (int ch = 0; ch < 4; ch++) {
            int idx = tid + ch * 256;           // 0..1023
            int row = idx >> 3;                 // 0..127
            int kq  = idx & 7;                  // float4 index along K
            int ks  = kq >> 1;                  // k-step (8-wide)
            int khi = (kq & 1);                 // kk>=4 half

            // A
            {
                float4 a4 = *(const float4*)(A + (size_t)(bm + row) * K + kt + kq * 4);
                int mt = row >> 4, mm = row & 15;
                int lidx_base = (mm & 7) * 4;
                int reg_base  = khi * 2 + (mm >> 3);
                uint32_t* dst = &As[((ks * 8 + mt) * 32 + lidx_base) * 4 + reg_base];
                dst[0]  = f2tf32(a4.x);
                dst[4]  = f2tf32(a4.y);
                dst[8]  = f2tf32(a4.z);
                dst[12] = f2tf32(a4.w);
            }
            // B (zero-pad rows beyond N)
            {
                float4 b4 = make_float4(0.f, 0.f, 0.f, 0.f);
                if (bn + row < N)
                    b4 = *(const float4*)(Bm + (size_t)(bn + row) * K + kt + kq * 4);
                int nt = row >> 3, nn = row & 7;
                int lidx_base = nn * 4;
                int reg_base  = khi;
                uint32_t* dst = &Bs[((ks * 16 + nt) * 32 + lidx_base) * 2 + reg_base];
                dst[0] = f2tf32(b4.x);
                dst[2] = f2tf32(b4.y);
                dst[4] = f2tf32(b4.z);
                dst[6] = f2tf32(b4.w);
            }
        }
        __syncthreads();

        // ---- mma main loop ----
        #pragma unroll
        for (int ks = 0; ks < 4; ks++) {
            uint32_t af[4][4];
            uint32_t bf[4][2];
            #pragma unroll
            for (int mt = 0; mt < 4; mt++) {
                uint4 v = *(const uint4*)&As[((ks * 8 + wm * 4 + mt) * 32 + lane) * 4];
                af[mt][0] = v.x; af[mt][1] = v.y; af[mt][2] = v.z; af[mt][3] = v.w;
            }
            #pragma unroll
            for (int nt = 0; nt < 4; nt++) {
                uint2 v = *(const uint2*)&Bs[((ks * 16 + wn * 4 + nt) * 32 + lane) * 2];
                bf[nt][0] = v.x; bf[nt][1] = v.y;
            }
            #pragma unroll
            for (int mt = 0; mt < 4; mt++)
                #pragma unroll
                for (int nt = 0; nt < 4; nt++) {
                    asm volatile(
                        "mma.sync.aligned.m16n8k8.row.col.f32.tf32.tf32.f32 "
                        "{%0,%1,%2,%3}, {%4,%5,%6,%7}, {%8,%9}, {%0,%1,%2,%3};"
                        : "+f"(acc[mt][nt][0]), "+f"(acc[mt][nt][1]),
                          "+f"(acc[mt][nt][2]), "+f"(acc[mt][nt][3])
                        : "r"(af[mt][0]), "r"(af[mt][1]),
                          "r"(af[mt][2]), "r"(af[mt][3]),
                          "r"(bf[nt][0]), "r"(bf[nt][1]));
                }
        }
        __syncthreads();
    }

    // ---- epilogue: bias + activation, float2 stores ----
    #pragma unroll
    for (int mt = 0; mt < 4; mt++) {
        int r0 = bm + wm * 64 + mt * 16 + (lane >> 2);
        #pragma unroll
        for (int nt = 0; nt < 4; nt++) {
            int c0 = bn + wn * 32 + nt * 8 + (lane & 3) * 2;
            if (c0 >= N) continue;            // N is even, pair is safe
            float bsum = 0.f;
            float bsum1 = 0.f;
            if (bias1) { bsum += bias1[c0]; bsum1 += bias1[c0 + 1]; }
            if (bias2) { bsum += bias2[c0]; bsum1 += bias2[c0 + 1]; }
            #pragma unroll
            for (int half = 0; half < 2; half++) {
                int row = r0 + half * 8;
                float v0 = acc[mt][nt][half * 2 + 0] + bsum;
                float v1 = acc[mt][nt][half * 2 + 1] + bsum1;
                if (OP == 1)      { v0 = tanhf(v0); v1 = tanhf(v1); }
                else if (OP == 2) { v0 = 1.f / (1.f + expf(-v0));
                                    v1 = 1.f / (1.f + expf(-v1)); }
                *(float2*)(C + (size_t)row * N + c0) = make_float2(v0, v1);
            }
        }
    }
}

// ---------------- persistent LSTM (128 CTAs, grid barrier) ------------------
__device__ __forceinline__ void grid_barrier(int ncta)
{
    __threadfence();
    __syncthreads();
    if (threadIdx.x == 0) {
        volatile unsigned* ph_p = &g_bar_phase;
        unsigned ph = *ph_p;
        unsigned prev = atomicAdd(&g_bar_count, 1u);
        if (prev == (unsigned)(ncta - 1)) {
            g_bar_count = 0;
            __threadfence();
            *ph_p = ph + 1;
        } else {
            while (*ph_p == ph) { __nanosleep(32); }
        }
    }
    __syncthreads();
}

// Each CTA owns 4 hidden units (16 gate rows of W_hh) cached in SMEM forever.
__global__ void __launch_bounds__(256)
lstm_kernel(const float* __restrict__ xpre, const float* __restrict__ W_hh,
            float* __restrict__ hout)
{
    extern __shared__ float sm[];
    float* W_s = sm;                 // 16 rows x 516 (padded)
    float* h_s = sm + 16 * 516;      // 32 x 512
    __shared__ float gate_s[32][16];
    __shared__ float c_s[32][4];

    const int tid = threadIdx.x;
    const int cta = blockIdx.x;
    const int bg = tid >> 4;         // 0..15 -> batches (2*bg, 2*bg+1)
    const int r  = tid & 15;         // 0..15 -> gate row within slice
    const int b0 = bg * 2, b1 = bg * 2 + 1;
    const int grow = (r >> 2) * 512 + cta * 4 + (r & 3); // global gate row

    for (int i = tid; i < 16 * 512; i += 256) {
        int rr = i >> 9, kk = i & 511;
        int gr = (rr >> 2) * 512 + cta * 4 + (rr & 3);
        W_s[rr * 516 + kk] = W_hh[(size_t)gr * 512 + kk];
    }
    if (tid < 128) c_s[tid >> 2][tid & 3] = 0.f;
    __syncthreads();

    const float4* Wr4 = (const float4*)(W_s + r * 516);
    const float4* H04 = (const float4*)(h_s + b0 * 512);
    const float4* H14 = (const float4*)(h_s + b1 * 512);

    for (int t = 0; t < LL; t++) {
        if (t > 0) {
            for (int i = tid; i < 32 * 128; i += 256) {
                int b = i >> 7, kq = i & 127;
                ((float4*)h_s)[b * 128 + kq] =
                    __ldcg(((const float4*)hout) + ((size_t)b * LL + (t - 1)) * 128 + kq);
            }
        }
        __syncthreads();

        float4 A0 = make_float4(0,0,0,0), A1 = make_float4(0,0,0,0);
        if (t > 0) {
            #pragma unroll 8
            for (int kq = 0; kq < 128; kq++) {
                float4 w  = Wr4[kq];
                float4 x0 = H04[kq];
                float4 x1 = H14[kq];
                A0.x += w.x * x0.x; A0.y += w.y * x0.y;
                A0.z += w.z * x0.z; A0.w += w.w * x0.w;
                A1.x += w.x * x1.x; A1.y += w.y * x1.y;
                A1.z += w.z * x1.z; A1.w += w.w * x1.w;
            }
        }
        float acc0 = (A0.x + A0.y) + (A0.z + A0.w);
        float acc1 = (A1.x + A1.y) + (A1.z + A1.w);
        acc0 += __ldg(xpre + ((size_t)b0 * LL + t) * G4 + grow);
        acc1 += __ldg(xpre + ((size_t)b1 * LL + t) * G4 + grow);
        gate_s[b0][r] = acc0;
        gate_s[b1][r] = acc1;
        __syncthreads();

        if (tid < 128) {
            int b = tid >> 2, u = tid & 3;
            float gi = gate_s[b][u];
            float gf = gate_s[b][4 + u];
            float gc = gate_s[b][8 + u];
            float go = gate_s[b][12 + u];
            float i_ = 1.f / (1.f + expf(-gi));
            float f_ = 1.f / (1.f + expf(-gf));
            float gg = tanhf(gc);
            float o_ = 1.f / (1.f + expf(-go));
            float c  = f_ * c_s[b][u] + i_ * gg;
            c_s[b][u] = c;
            hout[((size_t)b * LL + t) * HID + cta * 4 + u] = o_ * tanhf(c);
        }
        grid_barrier(LCTAS);
    }
}

// ---------------- att[m] = attT[m,:] . sim_W --------------------------------
__global__ void att_reduce(const float* __restrict__ attT,
                           const float* __restrict__ simW,
                           float* __restrict__ att)
{
    int gid  = blockIdx.x * blockDim.x + threadIdx.x;
    int row  = gid >> 5;
    int lane = threadIdx.x & 31;
    if (row >= BLROWS) return;
    float v = 0.f;
    for (int a = lane; a < ATTD; a += 32)
        v += attT[(size_t)row * ATTD + a] * simW[a];
    #pragma unroll
    for (int o = 16; o; o >>= 1) v += __shfl_down_sync(0xffffffffu, v, o);
    if (lane == 0) att[row] = v;
}

// ---------------- causal attention via online-softmax prefix scan -----------
__global__ void attn_scan(const float* __restrict__ att,
                          const float* __restrict__ out,
                          float* __restrict__ finalbuf)
{
    int b = blockIdx.x;          // 32 blocks
    int h = threadIdx.x;         // 512 threads
    __shared__ float s_att[LL];
    for (int i = h; i < LL; i += 512) s_att[i] = att[(size_t)b * LL + i];
    __syncthreads();

    const float* ob = out      + (size_t)b * LL * HID;
    float*       fb = finalbuf + (size_t)b * LL * (2 * HID);

    float m = -1e30f, den = 0.f, num = 0.f, cum = 0.f;
    for (int i = 0; i < LL; i++) {
        float s     = s_att[i];
        float mnew  = fmaxf(m, s);
        float scale = expf(m - mnew);
        float alpha = expf(s - mnew);
        float ov    = ob[(size_t)i * HID + h];
        num = num * scale + alpha * ov;
        den = den * scale + alpha;
        m   = mnew;
        fb[(size_t)i * (2 * HID) + h]       = cum;   // attn_cum_1 (exclusive)
        fb[(size_t)i * (2 * HID) + HID + h] = ov;    // out
        cum += num / den;
    }
}

// ---------------- launch -----------------------------------------------------
extern "C" void kernel_launch(void* const* d_in, const int* in_sizes, int n_in,
                              void* d_out, int out_size)
{
    const int*   skill        = (const int*)  d_in[0];
    const int*   answer       = (const int*)  d_in[1];
    const float* skill_table  = (const float*)d_in[2];
    const float* answer_table = (const float*)d_in[3];
    const float* W_ih         = (const float*)d_in[4];
    const float* W_hh         = (const float*)d_in[5];
    const float* b_ih         = (const float*)d_in[6];
    const float* b_hh         = (const float*)d_in[7];
    const float* mlp_W        = (const float*)d_in[8];
    const float* mlp_b        = (const float*)d_in[9];
    const float* sim_W        = (const float*)d_in[10];
    const float* fc_W         = (const float*)d_in[11];
    const float* fc_b         = (const float*)d_in[12];
    float* outp = (float*)d_out;

    float *p_sae, *p_xpre, *p_hout, *p_attT, *p_att, *p_final;
    cudaGetSymbolAddress((void**)&p_sae,   g_sae);
    cudaGetSymbolAddress((void**)&p_xpre,  g_xpre);
    cudaGetSymbolAddress((void**)&p_hout,  g_hout);
    cudaGetSymbolAddress((void**)&p_attT,  g_attT);
    cudaGetSymbolAddress((void**)&p_att,   g_att);
    cudaGetSymbolAddress((void**)&p_final, g_final);

    // 1) embeddings -> sae
    {
        int total = BLROWS * 128;
        embed_kernel<<<total / 256, 256>>>(skill, answer, skill_table, answer_table);
    }

    // 2) x_pre = sae @ W_ih^T + (b_ih + b_hh)      [tf32 tensor cores]
    {
        dim3 grid(G4 / 128, BLROWS / 128);
        tf32gemm_nt<0><<<grid, 256>>>(p_sae, W_ih, b_ih, b_hh, p_xpre,
                                      BLROWS, G4, HID);
    }

    // 3) LSTM recurrence (persistent, grid barrier)
    {
        const int smem = (16 * 516 + 32 * 512) * (int)sizeof(float);  // 98560
        cudaFuncSetAttribute(lstm_kernel,
                             cudaFuncAttributeMaxDynamicSharedMemorySize, smem);
        lstm_kernel<<<LCTAS, 256, smem>>>(p_xpre, W_hh, p_hout);
    }

    // 4) attT = tanh(out @ mlp_W^T + mlp_b)        [tf32 tensor cores]
    {
        dim3 grid((ATTD + 127) / 128, BLROWS / 128);
        tf32gemm_nt<1><<<grid, 256>>>(p_hout, mlp_W, mlp_b, nullptr, p_attT,
                                      BLROWS, ATTD, HID);
    }

    // 5) att = attT . sim_W
    att_reduce<<<(BLROWS * 32) / 256, 256>>>(p_attT, sim_W, p_att);

    // 6) online-softmax prefix scan -> final = [attn_cum_1, out]
    attn_scan<<<BB, 512>>>(p_att, p_hout, p_final);

    // 7) res = sigmoid(final @ fc_W^T + fc_b)      [tf32 tensor cores]
    {
        dim3 grid((NUMC + 127) / 128, BLROWS / 128);
        tf32gemm_nt<2><<<grid, 256>>>(p_final, fc_W, fc_b, nullptr, outp,
                                      BLROWS, NUMC, 2 * HID);
    }
}

// round 14
// speedup vs baseline: 1.2724x; 1.0892x over previous
#include <cuda_runtime.h>
#include <math.h>
#include <stdint.h>
#include <stdio.h>

#define BB    32
#define LL    1024
#define BLROWS (BB*LL)          // 32768
#define HID   512
#define G4    2048
#define NUMC  1000
#define ATTD  80
#define LCTAS 128

// ---------------- scratch (static device globals: allocation-free) ----------
__device__ float g_sae  [(size_t)BLROWS * HID];    // LSTM input rows
__device__ float g_xpre [(size_t)BLROWS * G4];     // x @ W_ih^T + b
__device__ float g_hout [(size_t)BLROWS * HID];    // LSTM hidden states ("out")
__device__ float g_hx   [2][HID * BB];             // transposed h exchange [k][b], parity buffered
__device__ float g_attT [(size_t)BLROWS * ATTD];   // tanh(out @ mlp_W^T + b)
__device__ float g_att  [BLROWS];                  // per-position attention logit
__device__ float g_final[(size_t)BLROWS * (2*HID)];// [attn_cum_1, out]
__device__ unsigned g_cnt[8 * 32];                 // group counters, 128B padded
__device__ unsigned g_root;
__device__ unsigned g_phase2;

// ---------------- embedding gather ------------------------------------------
__global__ void embed_kernel(const int* __restrict__ skill,
                             const int* __restrict__ answer,
                             const float* __restrict__ skill_table,
                             const float* __restrict__ answer_table)
{
    int idx = blockIdx.x * blockDim.x + threadIdx.x;   // over BLROWS*128 float4
    int row = idx >> 7;
    int q   = idx & 127;
    if (row >= BLROWS) return;
    int sk = skill[row];
    int an = answer[row];
    const float4* se = (const float4*)(skill_table  + (size_t)sk * 256);
    const float4* ae = (const float4*)(answer_table + (size_t)an * 256);
    float4 v;
    if (an == 1) v = (q < 64) ? se[q] : ae[q - 64];   // [skill, answer]
    else         v = (q < 64) ? ae[q] : se[q - 64];   // [answer, skill]
    ((float4*)g_sae)[(size_t)row * 128 + q] = v;
}

// ---------------- tf32 tensor-core GEMM: C = op(A @ B^T + bias1 + bias2) ----
// Double-buffered SMEM pipeline: tile k+1 LDG overlaps mma on tile k.
__device__ __forceinline__ uint32_t f2tf32(float v) {
    uint32_t u;
    asm("cvt.rna.tf32.f32 %0, %1;" : "=r"(u) : "f"(v));
    return u;
}

template<int OP>
__global__ void __launch_bounds__(256)
tf32gemm_nt(const float* __restrict__ A, const float* __restrict__ Bm,
            const float* __restrict__ bias1, const float* __restrict__ bias2,
            float* __restrict__ C, int M, int N, int K)
{
    // per buffer: A frags [ks(4)][mtile(8)][lane(32)][reg(4)], B frags [ks(4)][ntile(16)][lane(32)][reg(2)]
    __shared__ uint32_t As[2][4096];
    __shared__ uint32_t Bs[2][4096];

    const int tid  = threadIdx.x;
    const int warp = tid >> 5;
    const int lane = tid & 31;
    const int wm   = warp >> 2;      // 0..1
    const int wn   = warp & 3;       // 0..3
    const int bm   = blockIdx.y * 128;
    const int bn   = blockIdx.x * 128;

    float acc[4][4][4];
    #pragma unroll
    for (int i = 0; i < 4; i++)
        #pragma unroll
        for (int j = 0; j < 4; j++)
            #pragma unroll
            for (int r = 0; r < 4; r++) acc[i][j][r] = 0.f;

    int rowc[4], kqc[4];
    #pragma unroll
    for (int ch = 0; ch < 4; ch++) {
        int idx = tid + ch * 256;
        rowc[ch] = idx >> 3;
        kqc[ch]  = idx & 7;
    }

    float4 ra[4], rb[4];

    // ---- prologue: load + stage tile 0 into buffer 0 ----
    #pragma unroll
    for (int ch = 0; ch < 4; ch++) {
        ra[ch] = *(const float4*)(A + (size_t)(bm + rowc[ch]) * K + kqc[ch] * 4);
        rb[ch] = make_float4(0.f, 0.f, 0.f, 0.f);
        if (bn + rowc[ch] < N)
            rb[ch] = *(const float4*)(Bm + (size_t)(bn + rowc[ch]) * K + kqc[ch] * 4);
    }
    #pragma unroll
    for (int ch = 0; ch < 4; ch++) {
        int row = rowc[ch], kq = kqc[ch];
        int ks = kq >> 1, khi = kq & 1;
        {
            int mt = row >> 4, mm = row & 15;
            uint32_t* dst = &As[0][((ks * 8 + mt) * 32 + (mm & 7) * 4) * 4 + khi * 2 + (mm >> 3)];
            dst[0]  = f2tf32(ra[ch].x); dst[4]  = f2tf32(ra[ch].y);
            dst[8]  = f2tf32(ra[ch].z); dst[12] = f2tf32(ra[ch].w);
        }
        {
            int nt = row >> 3, nn = row & 7;
            uint32_t* dst = &Bs[0][((ks * 16 + nt) * 32 + nn * 4) * 2 + khi];
            dst[0] = f2tf32(rb[ch].x); dst[2] = f2tf32(rb[ch].y);
            dst[4] = f2tf32(rb[ch].z); dst[6] = f2tf32(rb[ch].w);
        }
    }
    __syncthreads();

    const int nkt = K >> 5;
    for (int kt = 0; kt < nkt; kt++) {
        const int cur = kt & 1;
        // prefetch next tile (overlaps with mma)
        if (kt + 1 < nkt) {
            int kofs = (kt + 1) * 32;
            #pragma unroll
            for (int ch = 0; ch < 4; ch++) {
                ra[ch] = *(const float4*)(A + (size_t)(bm + rowc[ch]) * K + kofs + kqc[ch] * 4);
                rb[ch] = make_float4(0.f, 0.f, 0.f, 0.f);
                if (bn + rowc[ch] < N)
                    rb[ch] = *(const float4*)(Bm + (size_t)(bn + rowc[ch]) * K + kofs + kqc[ch] * 4);
            }
        }

        // ---- mma on current buffer ----
        #pragma unroll
        for (int ks = 0; ks < 4; ks++) {
            uint32_t af[4][4];
            uint32_t bf[4][2];
            #pragma unroll
            for (int mt = 0; mt < 4; mt++) {
                uint4 v = *(const uint4*)&As[cur][((ks * 8 + wm * 4 + mt) * 32 + lane) * 4];
                af[mt][0] = v.x; af[mt][1] = v.y; af[mt][2] = v.z; af[mt][3] = v.w;
            }
            #pragma unroll
            for (int nt = 0; nt < 4; nt++) {
                uint2 v = *(const uint2*)&Bs[cur][((ks * 16 + wn * 4 + nt) * 32 + lane) * 2];
                bf[nt][0] = v.x; bf[nt][1] = v.y;
            }
            #pragma unroll
            for (int mt = 0; mt < 4; mt++)
                #pragma unroll
                for (int nt = 0; nt < 4; nt++) {
                    asm volatile(
                        "mma.sync.aligned.m16n8k8.row.col.f32.tf32.tf32.f32 "
                        "{%0,%1,%2,%3}, {%4,%5,%6,%7}, {%8,%9}, {%0,%1,%2,%3};"
                        : "+f"(acc[mt][nt][0]), "+f"(acc[mt][nt][1]),
                          "+f"(acc[mt][nt][2]), "+f"(acc[mt][nt][3])
                        : "r"(af[mt][0]), "r"(af[mt][1]),
                          "r"(af[mt][2]), "r"(af[mt][3]),
                          "r"(bf[nt][0]), "r"(bf[nt][1]));
                }
        }

        // stage next tile into other buffer
        if (kt + 1 < nkt) {
            const int nb = (kt + 1) & 1;
            #pragma unroll
            for (int ch = 0; ch < 4; ch++) {
                int row = rowc[ch], kq = kqc[ch];
                int ks = kq >> 1, khi = kq & 1;
                {
                    int mt = row >> 4, mm = row & 15;
                    uint32_t* dst = &As[nb][((ks * 8 + mt) * 32 + (mm & 7) * 4) * 4 + khi * 2 + (mm >> 3)];
                    dst[0]  = f2tf32(ra[ch].x); dst[4]  = f2tf32(ra[ch].y);
                    dst[8]  = f2tf32(ra[ch].z); dst[12] = f2tf32(ra[ch].w);
                }
                {
                    int nt = row >> 3, nn = row & 7;
                    uint32_t* dst = &Bs[nb][((ks * 16 + nt) * 32 + nn * 4) * 2 + khi];
                    dst[0] = f2tf32(rb[ch].x); dst[2] = f2tf32(rb[ch].y);
                    dst[4] = f2tf32(rb[ch].z); dst[6] = f2tf32(rb[ch].w);
                }
            }
        }
        __syncthreads();
    }

    // ---- epilogue: bias + activation, float2 stores ----
    #pragma unroll
    for (int mt = 0; mt < 4; mt++) {
        int r0 = bm + wm * 64 + mt * 16 + (lane >> 2);
        #pragma unroll
        for (int nt = 0; nt < 4; nt++) {
            int c0 = bn + wn * 32 + nt * 8 + (lane & 3) * 2;
            if (c0 >= N) continue;            // N is even, pair is safe
            float bsum = 0.f;
            float bsum1 = 0.f;
            if (bias1) { bsum += bias1[c0]; bsum1 += bias1[c0 + 1]; }
            if (bias2) { bsum += bias2[c0]; bsum1 += bias2[c0 + 1]; }
            #pragma unroll
            for (int half = 0; half < 2; half++) {
                int row = r0 + half * 8;
                float v0 = acc[mt][nt][half * 2 + 0] + bsum;
                float v1 = acc[mt][nt][half * 2 + 1] + bsum1;
                if (OP == 1)      { v0 = tanhf(v0); v1 = tanhf(v1); }
                else if (OP == 2) { v0 = 1.f / (1.f + expf(-v0));
                                    v1 = 1.f / (1.f + expf(-v1)); }
                *(float2*)(C + (size_t)row * N + c0) = make_float2(v0, v1);
            }
        }
    }
}

// ---------------- persistent LSTM v2 (128 CTAs) ------------------------------
// Warp = 8 gate-rows x 4 batch-groups; thread = 1 row x 4 batches x K/2.
// W_s [r][k] (stride 516): W-LDS.128 has 8 unique rows = 128B -> 1 wavefront.
// h_s transposed [k][b]: one LDS.128 serves a thread's 4 batches -> 1 wf.
// h exchanged via transposed global buffer g_hx, parity double-buffered.
// Grid barrier: two-level atomic tree (8 groups of 16 + root of 8).
__global__ void __launch_bounds__(256)
lstm_kernel(const float* __restrict__ xpre, const float* __restrict__ W_hh,
            float* __restrict__ hout)
{
    extern __shared__ float sm[];
    float* W_s = sm;                 // 16 rows x 516 (padded)
    float* h_s = sm + 16 * 516;      // [k][b]: 512 x 32
    __shared__ float gps[2][32][20]; // partial gate sums per k-half

    const int tid  = threadIdx.x;
    const int cta  = blockIdx.x;
    const int w    = tid >> 5;
    const int lane = tid & 31;
    const int kh     = w >> 2;          // k-half: 0 or 1
    const int rhalf  = w & 1;
    const int bgpair = (w >> 1) & 1;
    const int r  = rhalf * 8 + (lane & 7);    // gate row 0..15 (= gate*4 + unit)
    const int bg = bgpair * 4 + (lane >> 3);  // batch group 0..7 (4 batches each)

    // epilogue identity (threads 0..127): batch eb, unit eu
    const int eb = tid >> 2, eu = tid & 3;
    float c_reg = 0.f;

    // load W_hh slice once: row rr <-> gate rr>>2, unit rr&3
    for (int i = tid; i < 16 * 512; i += 256) {
        int rr = i >> 9, kk = i & 511;
        int gr = (rr >> 2) * 512 + cta * 4 + (rr & 3);
        W_s[rr * 516 + kk] = W_hh[(size_t)gr * 512 + kk];
    }
    __syncthreads();

    const float4* Wp = (const float4*)(W_s + r * 516 + kh * 256);
    const float*  Hp = h_s + kh * 256 * 32 + bg * 4;

    for (int t = 0; t < LL; t++) {
        // stage h(t-1) (transposed layout, straight 64KB copy from L2)
        if (t > 0) {
            const float4* src = (const float4*)g_hx[(t - 1) & 1];
            #pragma unroll
            for (int i = 0; i < 16; i++)
                ((float4*)h_s)[tid + i * 256] = __ldcg(src + tid + i * 256);
        }
        __syncthreads();

        // prefetch xpre for epilogue (latency hidden under FFMA phase)
        float xp0 = 0.f, xp1 = 0.f, xp2 = 0.f, xp3 = 0.f;
        if (tid < 128) {
            const float* xb = xpre + ((size_t)eb * LL + t) * G4 + cta * 4 + eu;
            xp0 = __ldg(xb);        xp1 = __ldg(xb + 512);
            xp2 = __ldg(xb + 1024); xp3 = __ldg(xb + 1536);
        }

        float4 acc = make_float4(0.f, 0.f, 0.f, 0.f);
        if (t > 0) {
            #pragma unroll 4
            for (int kq = 0; kq < 64; kq++) {
                float4 wv = Wp[kq];
                const float* hb = Hp + kq * 128;   // 4 consecutive k, each 32 wide
                float4 h0 = *(const float4*)(hb);
                float4 h1 = *(const float4*)(hb + 32);
                float4 h2 = *(const float4*)(hb + 64);
                float4 h3 = *(const float4*)(hb + 96);
                acc.x += wv.x * h0.x; acc.y += wv.x * h0.y;
                acc.z += wv.x * h0.z; acc.w += wv.x * h0.w;
                acc.x += wv.y * h1.x; acc.y += wv.y * h1.y;
                acc.z += wv.y * h1.z; acc.w += wv.y * h1.w;
                acc.x += wv.z * h2.x; acc.y += wv.z * h2.y;
                acc.z += wv.z * h2.z; acc.w += wv.z * h2.w;
                acc.x += wv.w * h3.x; acc.y += wv.w * h3.y;
                acc.z += wv.w * h3.z; acc.w += wv.w * h3.w;
            }
        }
        gps[kh][bg * 4 + 0][r] = acc.x;
        gps[kh][bg * 4 + 1][r] = acc.y;
        gps[kh][bg * 4 + 2][r] = acc.z;
        gps[kh][bg * 4 + 3][r] = acc.w;
        __syncthreads();

        if (tid < 128) {
            float gi = gps[0][eb][eu]       + gps[1][eb][eu]       + xp0;
            float gf = gps[0][eb][4 + eu]   + gps[1][eb][4 + eu]   + xp1;
            float gc = gps[0][eb][8 + eu]   + gps[1][eb][8 + eu]   + xp2;
            float go = gps[0][eb][12 + eu]  + gps[1][eb][12 + eu]  + xp3;
            float i_ = 1.f / (1.f + expf(-gi));
            float f_ = 1.f / (1.f + expf(-gf));
            float gg = tanhf(gc);
            float o_ = 1.f / (1.f + expf(-go));
            c_reg = f_ * c_reg + i_ * gg;
            float hv = o_ * tanhf(c_reg);
            g_hx[t & 1][(cta * 4 + eu) * 32 + eb] = hv;
            hout[((size_t)eb * LL + t) * HID + cta * 4 + eu] = hv;
        }

        // ---- two-level grid barrier ----
        __threadfence();
        __syncthreads();
        if (tid == 0) {
            volatile unsigned* php = &g_phase2;
            unsigned ph = *php;
            unsigned a = atomicAdd(&g_cnt[(cta >> 4) * 32], 1u);
            if (a == 15u) {
                unsigned rt = atomicAdd(&g_root, 1u);
                if (rt == 7u) {
                    #pragma unroll
                    for (int g2 = 0; g2 < 8; g2++) g_cnt[g2 * 32] = 0u;
                    g_root = 0u;
                    __threadfence();
                    *php = ph + 1u;
                }
            }
            while (*php == ph) { __nanosleep(32); }
        }
        __syncthreads();
    }
}

// ---------------- att[m] = attT[m,:] . sim_W --------------------------------
__global__ void att_reduce(const float* __restrict__ attT,
                           const float* __restrict__ simW,
                           float* __restrict__ att)
{
    int gid  = blockIdx.x * blockDim.x + threadIdx.x;
    int row  = gid >> 5;
    int lane = threadIdx.x & 31;
    if (row >= BLROWS) return;
    float v = 0.f;
    for (int a = lane; a < ATTD; a += 32)
        v += attT[(size_t)row * ATTD + a] * simW[a];
    #pragma unroll
    for (int o = 16; o; o >>= 1) v += __shfl_down_sync(0xffffffffu, v, o);
    if (lane == 0) att[row] = v;
}

// ---------------- causal attention via online-softmax prefix scan -----------
__global__ void attn_scan(const float* __restrict__ att,
                          const float* __restrict__ out,
                          float* __restrict__ finalbuf)
{
    int b = blockIdx.x;          // 32 blocks
    int h = threadIdx.x;         // 512 threads
    __shared__ float s_att[LL];
    for (int i = h; i < LL; i += 512) s_att[i] = att[(size_t)b * LL + i];
    __syncthreads();

    const float* ob = out      + (size_t)b * LL * HID;
    float*       fb = finalbuf + (size_t)b * LL * (2 * HID);

    float m = -1e30f, den = 0.f, num = 0.f, cum = 0.f;
    for (int i = 0; i < LL; i++) {
        float s     = s_att[i];
        float mnew  = fmaxf(m, s);
        float scale = expf(m - mnew);
        float alpha = expf(s - mnew);
        float ov    = ob[(size_t)i * HID + h];
        num = num * scale + alpha * ov;
        den = den * scale + alpha;
        m   = mnew;
        fb[(size_t)i * (2 * HID) + h]       = cum;   // attn_cum_1 (exclusive)
        fb[(size_t)i * (2 * HID) + HID + h] = ov;    // out
        cum += num / den;
    }
}

// ---------------- launch -----------------------------------------------------
extern "C" void kernel_launch(void* const* d_in, const int* in_sizes, int n_in,
                              void* d_out, int out_size)
{
    const int*   skill        = (const int*)  d_in[0];
    const int*   answer       = (const int*)  d_in[1];
    const float* skill_table  = (const float*)d_in[2];
    const float* answer_table = (const float*)d_in[3];
    const float* W_ih         = (const float*)d_in[4];
    const float* W_hh         = (const float*)d_in[5];
    const float* b_ih         = (const float*)d_in[6];
    const float* b_hh         = (const float*)d_in[7];
    const float* mlp_W        = (const float*)d_in[8];
    const float* mlp_b        = (const float*)d_in[9];
    const float* sim_W        = (const float*)d_in[10];
    const float* fc_W         = (const float*)d_in[11];
    const float* fc_b         = (const float*)d_in[12];
    float* outp = (float*)d_out;

    float *p_sae, *p_xpre, *p_hout, *p_attT, *p_att, *p_final;
    cudaGetSymbolAddress((void**)&p_sae,   g_sae);
    cudaGetSymbolAddress((void**)&p_xpre,  g_xpre);
    cudaGetSymbolAddress((void**)&p_hout,  g_hout);
    cudaGetSymbolAddress((void**)&p_attT,  g_attT);
    cudaGetSymbolAddress((void**)&p_att,   g_att);
    cudaGetSymbolAddress((void**)&p_final, g_final);

    // 1) embeddings -> sae
    {
        int total = BLROWS * 128;
        embed_kernel<<<total / 256, 256>>>(skill, answer, skill_table, answer_table);
    }

    // 2) x_pre = sae @ W_ih^T + (b_ih + b_hh)      [tf32 tensor cores]
    {
        dim3 grid(G4 / 128, BLROWS / 128);
        tf32gemm_nt<0><<<grid, 256>>>(p_sae, W_ih, b_ih, b_hh, p_xpre,
                                      BLROWS, G4, HID);
    }

    // 3) LSTM recurrence (persistent, two-level grid barrier)
    {
        const int smem = (16 * 516 + 512 * 32) * (int)sizeof(float);  // 98560
        cudaFuncSetAttribute(lstm_kernel,
                             cudaFuncAttributeMaxDynamicSharedMemorySize, smem);
        lstm_kernel<<<LCTAS, 256, smem>>>(p_xpre, W_hh, p_hout);
    }

    // 4) attT = tanh(out @ mlp_W^T + mlp_b)        [tf32 tensor cores]
    {
        dim3 grid((ATTD + 127) / 128, BLROWS / 128);
        tf32gemm_nt<1><<<grid, 256>>>(p_hout, mlp_W, mlp_b, nullptr, p_attT,
                                      BLROWS, ATTD, HID);
    }

    // 5) att = attT . sim_W
    att_reduce<<<(BLROWS * 32) / 256, 256>>>(p_attT, sim_W, p_att);

    // 6) online-softmax prefix scan -> final = [attn_cum_1, out]
    attn_scan<<<BB, 512>>>(p_att, p_hout, p_final);

    // 7) res = sigmoid(final @ fc_W^T + fc_b)      [tf32 tensor cores]
    {
        dim3 grid((NUMC + 127) / 128, BLROWS / 128);
        tf32gemm_nt<2><<<grid, 256>>>(p_final, fc_W, fc_b, nullptr, outp,
                                      BLROWS, NUMC, 2 * HID);
    }
}

// round 15
// speedup vs baseline: 1.3614x; 1.0700x over previous
#include <cuda_runtime.h>
#include <math.h>
#include <stdint.h>
#include <stdio.h>

#define BB    32
#define LL    1024
#define BLROWS (BB*LL)          // 32768
#define HID   512
#define G4    2048
#define NUMC  1000
#define ATTD  80

// LSTM partition: 4 independent groups x 32 CTAs; each group owns 8 batches.
#define NGRP  4
#define GCTAS 32
#define GBATCH 8

// ---------------- scratch (static device globals: allocation-free) ----------
__device__ float g_sae  [(size_t)BLROWS * HID];    // LSTM input rows
__device__ float g_xpre [(size_t)BLROWS * G4];     // x @ W_ih^T + b
__device__ float g_hout [(size_t)BLROWS * HID];    // LSTM hidden states ("out")
__device__ float g_hx   [2][NGRP][HID * GBATCH];   // transposed h exchange [k][b], parity buffered
__device__ float g_attT [(size_t)BLROWS * ATTD];   // tanh(out @ mlp_W^T + b)
__device__ float g_att  [BLROWS];                  // per-position attention logit
__device__ float g_final[(size_t)BLROWS * (2*HID)];// [attn_cum_1, out]
__device__ unsigned g_cnt[NGRP * 32];              // per-group arrival counters (128B padded)
__device__ unsigned g_ph [NGRP * 32];              // per-group phases (128B padded)

// ---------------- embedding gather ------------------------------------------
__global__ void embed_kernel(const int* __restrict__ skill,
                             const int* __restrict__ answer,
                             const float* __restrict__ skill_table,
                             const float* __restrict__ answer_table)
{
    int idx = blockIdx.x * blockDim.x + threadIdx.x;   // over BLROWS*128 float4
    int row = idx >> 7;
    int q   = idx & 127;
    if (row >= BLROWS) return;
    int sk = skill[row];
    int an = answer[row];
    const float4* se = (const float4*)(skill_table  + (size_t)sk * 256);
    const float4* ae = (const float4*)(answer_table + (size_t)an * 256);
    float4 v;
    if (an == 1) v = (q < 64) ? se[q] : ae[q - 64];   // [skill, answer]
    else         v = (q < 64) ? ae[q] : se[q - 64];   // [answer, skill]
    ((float4*)g_sae)[(size_t)row * 128 + q] = v;
}

// ---------------- tf32 tensor-core GEMM: C = op(A @ B^T + bias1 + bias2) ----
__device__ __forceinline__ uint32_t f2tf32(float v) {
    uint32_t u;
    asm("cvt.rna.tf32.f32 %0, %1;" : "=r"(u) : "f"(v));
    return u;
}

template<int OP>
__global__ void __launch_bounds__(256)
tf32gemm_nt(const float* __restrict__ A, const float* __restrict__ Bm,
            const float* __restrict__ bias1, const float* __restrict__ bias2,
            float* __restrict__ C, int M, int N, int K)
{
    __shared__ uint32_t As[2][4096];
    __shared__ uint32_t Bs[2][4096];

    const int tid  = threadIdx.x;
    const int warp = tid >> 5;
    const int lane = tid & 31;
    const int wm   = warp >> 2;      // 0..1
    const int wn   = warp & 3;       // 0..3
    const int bm   = blockIdx.y * 128;
    const int bn   = blockIdx.x * 128;

    float acc[4][4][4];
    #pragma unroll
    for (int i = 0; i < 4; i++)
        #pragma unroll
        for (int j = 0; j < 4; j++)
            #pragma unroll
            for (int r = 0; r < 4; r++) acc[i][j][r] = 0.f;

    int rowc[4], kqc[4];
    #pragma unroll
    for (int ch = 0; ch < 4; ch++) {
        int idx = tid + ch * 256;
        rowc[ch] = idx >> 3;
        kqc[ch]  = idx & 7;
    }

    float4 ra[4], rb[4];

    #pragma unroll
    for (int ch = 0; ch < 4; ch++) {
        ra[ch] = *(const float4*)(A + (size_t)(bm + rowc[ch]) * K + kqc[ch] * 4);
        rb[ch] = make_float4(0.f, 0.f, 0.f, 0.f);
        if (bn + rowc[ch] < N)
            rb[ch] = *(const float4*)(Bm + (size_t)(bn + rowc[ch]) * K + kqc[ch] * 4);
    }
    #pragma unroll
    for (int ch = 0; ch < 4; ch++) {
        int row = rowc[ch], kq = kqc[ch];
        int ks = kq >> 1, khi = kq & 1;
        {
            int mt = row >> 4, mm = row & 15;
            uint32_t* dst = &As[0][((ks * 8 + mt) * 32 + (mm & 7) * 4) * 4 + khi * 2 + (mm >> 3)];
            dst[0]  = f2tf32(ra[ch].x); dst[4]  = f2tf32(ra[ch].y);
            dst[8]  = f2tf32(ra[ch].z); dst[12] = f2tf32(ra[ch].w);
        }
        {
            int nt = row >> 3, nn = row & 7;
            uint32_t* dst = &Bs[0][((ks * 16 + nt) * 32 + nn * 4) * 2 + khi];
            dst[0] = f2tf32(rb[ch].x); dst[2] = f2tf32(rb[ch].y);
            dst[4] = f2tf32(rb[ch].z); dst[6] = f2tf32(rb[ch].w);
        }
    }
    __syncthreads();

    const int nkt = K >> 5;
    for (int kt = 0; kt < nkt; kt++) {
        const int cur = kt & 1;
        if (kt + 1 < nkt) {
            int kofs = (kt + 1) * 32;
            #pragma unroll
            for (int ch = 0; ch < 4; ch++) {
                ra[ch] = *(const float4*)(A + (size_t)(bm + rowc[ch]) * K + kofs + kqc[ch] * 4);
                rb[ch] = make_float4(0.f, 0.f, 0.f, 0.f);
                if (bn + rowc[ch] < N)
                    rb[ch] = *(const float4*)(Bm + (size_t)(bn + rowc[ch]) * K + kofs + kqc[ch] * 4);
            }
        }

        #pragma unroll
        for (int ks = 0; ks < 4; ks++) {
            uint32_t af[4][4];
            uint32_t bf[4][2];
            #pragma unroll
            for (int mt = 0; mt < 4; mt++) {
                uint4 v = *(const uint4*)&As[cur][((ks * 8 + wm * 4 + mt) * 32 + lane) * 4];
                af[mt][0] = v.x; af[mt][1] = v.y; af[mt][2] = v.z; af[mt][3] = v.w;
            }
            #pragma unroll
            for (int nt = 0; nt < 4; nt++) {
                uint2 v = *(const uint2*)&Bs[cur][((ks * 16 + wn * 4 + nt) * 32 + lane) * 2];
                bf[nt][0] = v.x; bf[nt][1] = v.y;
            }
            #pragma unroll
            for (int mt = 0; mt < 4; mt++)
                #pragma unroll
                for (int nt = 0; nt < 4; nt++) {
                    asm volatile(
                        "mma.sync.aligned.m16n8k8.row.col.f32.tf32.tf32.f32 "
                        "{%0,%1,%2,%3}, {%4,%5,%6,%7}, {%8,%9}, {%0,%1,%2,%3};"
                        : "+f"(acc[mt][nt][0]), "+f"(acc[mt][nt][1]),
                          "+f"(acc[mt][nt][2]), "+f"(acc[mt][nt][3])
                        : "r"(af[mt][0]), "r"(af[mt][1]),
                          "r"(af[mt][2]), "r"(af[mt][3]),
                          "r"(bf[nt][0]), "r"(bf[nt][1]));
                }
        }

        if (kt + 1 < nkt) {
            const int nb = (kt + 1) & 1;
            #pragma unroll
            for (int ch = 0; ch < 4; ch++) {
                int row = rowc[ch], kq = kqc[ch];
                int ks = kq >> 1, khi = kq & 1;
                {
                    int mt = row >> 4, mm = row & 15;
                    uint32_t* dst = &As[nb][((ks * 8 + mt) * 32 + (mm & 7) * 4) * 4 + khi * 2 + (mm >> 3)];
                    dst[0]  = f2tf32(ra[ch].x); dst[4]  = f2tf32(ra[ch].y);
                    dst[8]  = f2tf32(ra[ch].z); dst[12] = f2tf32(ra[ch].w);
                }
                {
                    int nt = row >> 3, nn = row & 7;
                    uint32_t* dst = &Bs[nb][((ks * 16 + nt) * 32 + nn * 4) * 2 + khi];
                    dst[0] = f2tf32(rb[ch].x); dst[2] = f2tf32(rb[ch].y);
                    dst[4] = f2tf32(rb[ch].z); dst[6] = f2tf32(rb[ch].w);
                }
            }
        }
        __syncthreads();
    }

    #pragma unroll
    for (int mt = 0; mt < 4; mt++) {
        int r0 = bm + wm * 64 + mt * 16 + (lane >> 2);
        #pragma unroll
        for (int nt = 0; nt < 4; nt++) {
            int c0 = bn + wn * 32 + nt * 8 + (lane & 3) * 2;
            if (c0 >= N) continue;            // N is even, pair is safe
            float bsum = 0.f;
            float bsum1 = 0.f;
            if (bias1) { bsum += bias1[c0]; bsum1 += bias1[c0 + 1]; }
            if (bias2) { bsum += bias2[c0]; bsum1 += bias2[c0 + 1]; }
            #pragma unroll
            for (int half = 0; half < 2; half++) {
                int row = r0 + half * 8;
                float v0 = acc[mt][nt][half * 2 + 0] + bsum;
                float v1 = acc[mt][nt][half * 2 + 1] + bsum1;
                if (OP == 1)      { v0 = tanhf(v0); v1 = tanhf(v1); }
                else if (OP == 2) { v0 = 1.f / (1.f + expf(-v0));
                                    v1 = 1.f / (1.f + expf(-v1)); }
                *(float2*)(C + (size_t)row * N + c0) = make_float2(v0, v1);
            }
        }
    }
}

// ---------------- persistent LSTM v3: 4 groups x 32 CTAs --------------------
// Group g owns batches [g*8, g*8+8) and ALL 2048 gate rows (64 rows/CTA,
// W slice 133KB SMEM-resident). Groups are fully independent: per-group
// barrier (32 arrivals) and per-group transposed h exchange buffer.
// Warp layout: 16 rows x 2 batch-groups, fixed k-half per warp-half.
__global__ void __launch_bounds__(256)
lstm_kernel(const float* __restrict__ xpre, const float* __restrict__ W_hh,
            float* __restrict__ hout)
{
    extern __shared__ float sm[];
    float* W_s = sm;                   // 64 rows x 520 (padded)
    float* h_s = sm + 64 * 520;        // [k][b]: 512 x 8
    __shared__ float gps[2][GBATCH][68];  // partial gate sums per k-half

    const int tid  = threadIdx.x;
    const int grp  = blockIdx.x >> 5;       // 0..3
    const int cig  = blockIdx.x & 31;       // CTA within group
    const int w    = tid >> 5;
    const int lane = tid & 31;
    const int r16  = lane & 15;
    const int bg   = lane >> 4;              // 0..1 (batches bg*4..bg*4+3)
    const int kh   = w >> 2;                 // k-half
    const int row  = (w & 3) * 16 + r16;     // 0..63 = gate*16 + unit

    // epilogue identity (threads 0..127): batch eb (0..7), unit eu (0..15)
    const int eb = tid >> 4, eu = tid & 15;
    float c_reg = 0.f;

    // load W_hh slice once: local row rr = gate*16 + unit
    for (int i = tid; i < 64 * 512; i += 256) {
        int rr = i >> 9, kk = i & 511;
        int gr = (rr >> 4) * 512 + cig * 16 + (rr & 15);
        W_s[rr * 520 + kk] = W_hh[(size_t)gr * 512 + kk];
    }
    __syncthreads();

    const float4* Wp = (const float4*)(W_s + row * 520 + kh * 256);
    const float*  Hp = h_s + kh * 256 * 8 + bg * 4;

    unsigned* cntp = &g_cnt[grp * 32];
    volatile unsigned* php = (volatile unsigned*)&g_ph[grp * 32];

    for (int t = 0; t < LL; t++) {
        if (t > 0) {
            // stage h(t-1): 16KB transposed [k][8] copy from L2
            const float4* src = (const float4*)&g_hx[(t - 1) & 1][grp][0];
            float4* dst = (float4*)h_s;
            #pragma unroll
            for (int i = 0; i < 4; i++)
                dst[tid + i * 256] = __ldcg(src + tid + i * 256);
        }
        __syncthreads();

        // prefetch xpre for epilogue (latency hidden under FFMA phase)
        float xp0 = 0.f, xp1 = 0.f, xp2 = 0.f, xp3 = 0.f;
        if (tid < 128) {
            const float* xb = xpre + ((size_t)(grp * GBATCH + eb) * LL + t) * G4 + cig * 16 + eu;
            xp0 = __ldg(xb);        xp1 = __ldg(xb + 512);
            xp2 = __ldg(xb + 1024); xp3 = __ldg(xb + 1536);
        }

        float4 acc = make_float4(0.f, 0.f, 0.f, 0.f);
        if (t > 0) {
            #pragma unroll 4
            for (int kq = 0; kq < 64; kq++) {
                float4 wv = Wp[kq];
                const float* hb = Hp + kq * 32;   // 4 consecutive k, each 8 wide
                float4 h0 = *(const float4*)(hb);
                float4 h1 = *(const float4*)(hb + 8);
                float4 h2 = *(const float4*)(hb + 16);
                float4 h3 = *(const float4*)(hb + 24);
                acc.x += wv.x * h0.x; acc.y += wv.x * h0.y;
                acc.z += wv.x * h0.z; acc.w += wv.x * h0.w;
                acc.x += wv.y * h1.x; acc.y += wv.y * h1.y;
                acc.z += wv.y * h1.z; acc.w += wv.y * h1.w;
                acc.x += wv.z * h2.x; acc.y += wv.z * h2.y;
                acc.z += wv.z * h2.z; acc.w += wv.z * h2.w;
                acc.x += wv.w * h3.x; acc.y += wv.w * h3.y;
                acc.z += wv.w * h3.z; acc.w += wv.w * h3.w;
            }
        }
        gps[kh][bg * 4 + 0][row] = acc.x;
        gps[kh][bg * 4 + 1][row] = acc.y;
        gps[kh][bg * 4 + 2][row] = acc.z;
        gps[kh][bg * 4 + 3][row] = acc.w;
        __syncthreads();

        if (tid < 128) {
            float gi = gps[0][eb][eu]      + gps[1][eb][eu]      + xp0;
            float gf = gps[0][eb][16 + eu] + gps[1][eb][16 + eu] + xp1;
            float gc = gps[0][eb][32 + eu] + gps[1][eb][32 + eu] + xp2;
            float go = gps[0][eb][48 + eu] + gps[1][eb][48 + eu] + xp3;
            float i_ = 1.f / (1.f + expf(-gi));
            float f_ = 1.f / (1.f + expf(-gf));
            float gg = tanhf(gc);
            float o_ = 1.f / (1.f + expf(-go));
            c_reg = f_ * c_reg + i_ * gg;
            float hv = o_ * tanhf(c_reg);
            g_hx[t & 1][grp][(cig * 16 + eu) * GBATCH + eb] = hv;
            hout[((size_t)(grp * GBATCH + eb) * LL + t) * HID + cig * 16 + eu] = hv;
        }

        // ---- per-group barrier (32 arrivals, single level) ----
        __threadfence();
        __syncthreads();
        if (tid == 0) {
            unsigned ph = *php;
            if (atomicAdd(cntp, 1u) == (GCTAS - 1u)) {
                *cntp = 0u;
                __threadfence();
                *php = ph + 1u;
            } else {
                while (*php == ph) { __nanosleep(16); }
            }
        }
        __syncthreads();
    }
}

// ---------------- att[m] = attT[m,:] . sim_W --------------------------------
__global__ void att_reduce(const float* __restrict__ attT,
                           const float* __restrict__ simW,
                           float* __restrict__ att)
{
    int gid  = blockIdx.x * blockDim.x + threadIdx.x;
    int row  = gid >> 5;
    int lane = threadIdx.x & 31;
    if (row >= BLROWS) return;
    float v = 0.f;
    for (int a = lane; a < ATTD; a += 32)
        v += attT[(size_t)row * ATTD + a] * simW[a];
    #pragma unroll
    for (int o = 16; o; o >>= 1) v += __shfl_down_sync(0xffffffffu, v, o);
    if (lane == 0) att[row] = v;
}

// ---------------- causal attention via online-softmax prefix scan -----------
// grid (BB, 4), block 128: CTA handles batch b, h-chunk of 128.
__global__ void attn_scan(const float* __restrict__ att,
                          const float* __restrict__ out,
                          float* __restrict__ finalbuf)
{
    int b = blockIdx.x;
    int h = blockIdx.y * 128 + threadIdx.x;
    __shared__ float s_att[LL];
    for (int i = threadIdx.x; i < LL; i += 128) s_att[i] = att[(size_t)b * LL + i];
    __syncthreads();

    const float* ob = out      + (size_t)b * LL * HID + h;
    float*       fb = finalbuf + (size_t)b * LL * (2 * HID) + h;

    float m = -1e30f, den = 0.f, num = 0.f, cum = 0.f;
    for (int i = 0; i < LL; i++) {
        float s     = s_att[i];
        float mnew  = fmaxf(m, s);
        float scale = expf(m - mnew);
        float alpha = expf(s - mnew);
        float ov    = ob[(size_t)i * HID];
        num = num * scale + alpha * ov;
        den = den * scale + alpha;
        m   = mnew;
        fb[(size_t)i * (2 * HID)]       = cum;   // attn_cum_1 (exclusive)
        fb[(size_t)i * (2 * HID) + HID] = ov;    // out
        cum += num / den;
    }
}

// ---------------- launch -----------------------------------------------------
extern "C" void kernel_launch(void* const* d_in, const int* in_sizes, int n_in,
                              void* d_out, int out_size)
{
    const int*   skill        = (const int*)  d_in[0];
    const int*   answer       = (const int*)  d_in[1];
    const float* skill_table  = (const float*)d_in[2];
    const float* answer_table = (const float*)d_in[3];
    const float* W_ih         = (const float*)d_in[4];
    const float* W_hh         = (const float*)d_in[5];
    const float* b_ih         = (const float*)d_in[6];
    const float* b_hh         = (const float*)d_in[7];
    const float* mlp_W        = (const float*)d_in[8];
    const float* mlp_b        = (const float*)d_in[9];
    const float* sim_W        = (const float*)d_in[10];
    const float* fc_W         = (const float*)d_in[11];
    const float* fc_b         = (const float*)d_in[12];
    float* outp = (float*)d_out;

    float *p_sae, *p_xpre, *p_hout, *p_attT, *p_att, *p_final;
    cudaGetSymbolAddress((void**)&p_sae,   g_sae);
    cudaGetSymbolAddress((void**)&p_xpre,  g_xpre);
    cudaGetSymbolAddress((void**)&p_hout,  g_hout);
    cudaGetSymbolAddress((void**)&p_attT,  g_attT);
    cudaGetSymbolAddress((void**)&p_att,   g_att);
    cudaGetSymbolAddress((void**)&p_final, g_final);

    // 1) embeddings -> sae
    {
        int total = BLROWS * 128;
        embed_kernel<<<total / 256, 256>>>(skill, answer, skill_table, answer_table);
    }

    // 2) x_pre = sae @ W_ih^T + (b_ih + b_hh)      [tf32 tensor cores]
    {
        dim3 grid(G4 / 128, BLROWS / 128);
        tf32gemm_nt<0><<<grid, 256>>>(p_sae, W_ih, b_ih, b_hh, p_xpre,
                                      BLROWS, G4, HID);
    }

    // 3) LSTM recurrence (4 independent groups of 32 CTAs)
    {
        const int smem = (64 * 520 + 512 * GBATCH) * (int)sizeof(float);  // 149504
        cudaFuncSetAttribute(lstm_kernel,
                             cudaFuncAttributeMaxDynamicSharedMemorySize, smem);
        lstm_kernel<<<NGRP * GCTAS, 256, smem>>>(p_xpre, W_hh, p_hout);
    }

    // 4) attT = tanh(out @ mlp_W^T + mlp_b)        [tf32 tensor cores]
    {
        dim3 grid((ATTD + 127) / 128, BLROWS / 128);
        tf32gemm_nt<1><<<grid, 256>>>(p_hout, mlp_W, mlp_b, nullptr, p_attT,
                                      BLROWS, ATTD, HID);
    }

    // 5) att = attT . sim_W
    att_reduce<<<(BLROWS * 32) / 256, 256>>>(p_attT, sim_W, p_att);

    // 6) online-softmax prefix scan -> final = [attn_cum_1, out]
    {
        dim3 grid(BB, 4);
        attn_scan<<<grid, 128>>>(p_att, p_hout, p_final);
    }

    // 7) res = sigmoid(final @ fc_W^T + fc_b)      [tf32 tensor cores]
    {
        dim3 grid((NUMC + 127) / 128, BLROWS / 128);
        tf32gemm_nt<2><<<grid, 256>>>(p_final, fc_W, fc_b, nullptr, outp,
                                      BLROWS, NUMC, 2 * HID);
    }
}